// round 12
// baseline (speedup 1.0000x reference)
#include <cuda_runtime.h>
#include <cuda_fp16.h>
#include <cstdint>
#include <cstddef>

// ---------------------------------------------------------------------------
// Problem constants
// ---------------------------------------------------------------------------
#define BWIN 2048
#define NTOK 50
#define CDIM 256
#define NH   8
#define HD   32
#define MROWS (BWIN * NTOK)      // 102400
#define GK   256                 // GEMM K

// ---------------------------------------------------------------------------
// Scratch (device globals; no allocation allowed)
// ---------------------------------------------------------------------------
__device__ __half g_xh[(size_t)MROWS * GK];        // x rounded fp16
__device__ __half g_qkvh[(size_t)MROWS * 768];     // qkv hi fp16
__device__ __half g_qkvl[(size_t)MROWS * 768];     // qkv lo fp16
__device__ __half g_oh[(size_t)MROWS * CDIM];      // attention out fp16 (rounded)
__device__ __half g_wqh[768 * GK], g_wql[768 * GK];
__device__ __half g_wph[CDIM * GK];
__device__ float  g_qkvb[768];                     // qkv bias (q-scaled)
__device__ float  g_bias[NH * NTOK * NTOK + 64];   // expanded relpos bias

// ---------------------------------------------------------------------------
// Helpers
// ---------------------------------------------------------------------------
__device__ __forceinline__ uint32_t smem_u32(const void* p) {
    uint32_t a;
    asm("{ .reg .u64 t; cvta.to.shared.u64 t, %1; cvt.u32.u64 %0, t; }" : "=r"(a) : "l"(p));
    return a;
}

// fp32 pair -> packed fp16 hi pair + packed fp16 lo pair
__device__ __forceinline__ void split2h(float x, float y, uint32_t& hp, uint32_t& lp) {
    __half2 h = __floats2half2_rn(x, y);
    hp = *reinterpret_cast<uint32_t*>(&h);
    float rx = x - __low2float(h);
    float ry = y - __high2float(h);
    __half2 l = __floats2half2_rn(rx, ry);
    lp = *reinterpret_cast<uint32_t*>(&l);
}

#define LDSM_X4(r, a) asm volatile( \
    "ldmatrix.sync.aligned.m8n8.x4.shared.b16 {%0,%1,%2,%3}, [%4];" \
    : "=r"((r)[0]), "=r"((r)[1]), "=r"((r)[2]), "=r"((r)[3]) : "r"(a))
#define LDSM_X2(r, a) asm volatile( \
    "ldmatrix.sync.aligned.m8n8.x2.shared.b16 {%0,%1}, [%2];" \
    : "=r"((r)[0]), "=r"((r)[1]) : "r"(a))
#define LDSM_X4_T(r, a) asm volatile( \
    "ldmatrix.sync.aligned.m8n8.x4.trans.shared.b16 {%0,%1,%2,%3}, [%4];" \
    : "=r"((r)[0]), "=r"((r)[1]), "=r"((r)[2]), "=r"((r)[3]) : "r"(a))

// fp32-accumulator HMMA
__device__ __forceinline__ void mma16816h(float* d, const uint32_t* a, const uint32_t* b) {
    asm volatile(
        "mma.sync.aligned.m16n8k16.row.col.f32.f16.f16.f32 "
        "{%0,%1,%2,%3},{%4,%5,%6,%7},{%8,%9},{%0,%1,%2,%3};"
        : "+f"(d[0]), "+f"(d[1]), "+f"(d[2]), "+f"(d[3])
        : "r"(a[0]), "r"(a[1]), "r"(a[2]), "r"(a[3]), "r"(b[0]), "r"(b[1]));
}

// fp16-accumulator HMMA (2x rate hypothesis) — used for lo correction terms
__device__ __forceinline__ void mma16816hh(uint32_t* d, const uint32_t* a, const uint32_t* b) {
    asm volatile(
        "mma.sync.aligned.m16n8k16.row.col.f16.f16.f16.f16 "
        "{%0,%1},{%2,%3,%4,%5},{%6,%7},{%0,%1};"
        : "+r"(d[0]), "+r"(d[1])
        : "r"(a[0]), "r"(a[1]), "r"(a[2]), "r"(a[3]), "r"(b[0]), "r"(b[1]));
}

#define CP_ASYNC16(dst, src) asm volatile( \
    "cp.async.cg.shared.global [%0], [%1], 16;" :: "r"(dst), "l"(src))
#define CP_COMMIT() asm volatile("cp.async.commit_group;" ::: "memory")
#define CP_WAIT(n)  asm volatile("cp.async.wait_group %0;" :: "n"(n) : "memory")
#define STS64(a, x, y) asm volatile("st.shared.v2.b32 [%0], {%1,%2};" :: "r"(a), "r"(x), "r"(y) : "memory")

// 64B-row swizzle (attention tiles)
__device__ __forceinline__ uint32_t swz(uint32_t base, int r, int ch) {
    return base + r * 64 + 16 * (ch ^ ((r >> 1) & 3));
}
// 32B-row swizzle (GEMM k16 stages)
__device__ __forceinline__ uint32_t swz16(uint32_t base, int r, int ch) {
    return base + r * 32 + 16 * (ch ^ ((r >> 2) & 1));
}

// ---------------------------------------------------------------------------
// Converters
// ---------------------------------------------------------------------------
__global__ void conv_x(const float* __restrict__ src, __half* __restrict__ dh, int n4)
{
    int i = blockIdx.x * 256 + threadIdx.x;
    if (i >= n4) return;
    float4 v = ((const float4*)src)[i];
    __half2 h01 = __floats2half2_rn(v.x, v.y);
    __half2 h23 = __floats2half2_rn(v.z, v.w);
    ((uint2*)dh)[i] = make_uint2(*(uint32_t*)&h01, *(uint32_t*)&h23);
}

__global__ void conv_w(const float* __restrict__ src,
                       __half* __restrict__ dh, __half* __restrict__ dl,
                       int n4, int sth, float scale)
{
    int i = blockIdx.x * 256 + threadIdx.x;
    if (i >= n4) return;
    float4 v = ((const float4*)src)[i];
    if (i < sth) { v.x *= scale; v.y *= scale; v.z *= scale; v.w *= scale; }
    uint32_t h01, l01, h23, l23;
    split2h(v.x, v.y, h01, l01);
    split2h(v.z, v.w, h23, l23);
    ((uint2*)dh)[i] = make_uint2(h01, h23);
    ((uint2*)dl)[i] = make_uint2(l01, l23);
}

__global__ void conv_bias(const float* __restrict__ qkv_b, float scale)
{
    int i = threadIdx.x + blockIdx.x * 256;
    if (i < 768) g_qkvb[i] = qkv_b[i] * (i < 256 ? scale : 1.f);
}

__global__ void bias_expand(const float* __restrict__ bt, const int* __restrict__ ri)
{
    int idx = blockIdx.x * 256 + threadIdx.x;
    if (idx >= NH * NTOK * NTOK) return;
    int h = idx / (NTOK * NTOK);
    int rem = idx - h * NTOK * NTOK;
    int i = rem / NTOK, j = rem - i * NTOK;
    float v = 0.f;
    if (i > 0 && j > 0) v = bt[ri[(i - 1) * 49 + (j - 1)] * NH + h];
    g_bias[idx] = v;
}

// ---------------------------------------------------------------------------
// qk GEMM (2-split): hi term fp32-acc, lo term fp16-acc.
// 256 threads, 8 warps (2x4), warp tile 64x32, k16 x 3-stage ring.
// ---------------------------------------------------------------------------
#define GEMM_SMEM2 (3 * 12288)
#define GEMM_SMEM1 (3 * 8192)

__global__ void __launch_bounds__(256)
gemm_qk(const __half* __restrict__ Ah,
        const __half* __restrict__ Wh, const __half* __restrict__ Wl,
        const float* __restrict__ bias,
        __half* __restrict__ Ch, __half* __restrict__ Cl, int Nn)
{
    extern __shared__ char smem[];
    const uint32_t sbase = smem_u32(smem);
    constexpr uint32_t STG = 12288u;
    constexpr uint32_t OFF_BH = 4096u, OFF_BL = 8192u;
    constexpr int NSTAGE = 16;

    const int tid  = threadIdx.x;
    const int lane = tid & 31;
    const int warp = tid >> 5;
    const int m0 = blockIdx.y * 128;
    const int n0 = blockIdx.x * 128;
    const int wm = warp & 1;
    const int wn = warp >> 1;

    float    acc[4][4][4];
    uint32_t accH[4][4][2];
#pragma unroll
    for (int i = 0; i < 4; i++)
#pragma unroll
        for (int j = 0; j < 4; j++) {
#pragma unroll
            for (int r = 0; r < 4; r++) acc[i][j][r] = 0.f;
            accH[i][j][0] = 0u; accH[i][j][1] = 0u;
        }

    const int crow = tid >> 1;
    const int cch  = tid & 1;
    const uint32_t cdst = swz16(0, crow, cch);
    const __half* srcA  = Ah + (size_t)(m0 + crow) * GK + cch * 8;
    const __half* srcBh = Wh + (size_t)(n0 + crow) * GK + cch * 8;
    const __half* srcBl = Wl + (size_t)(n0 + crow) * GK + cch * 8;

    auto issue = [&](int s) {
        const uint32_t stb = sbase + (uint32_t)(s % 3) * STG;
        CP_ASYNC16(stb + cdst,          srcA  + s * 16);
        CP_ASYNC16(stb + OFF_BH + cdst, srcBh + s * 16);
        CP_ASYNC16(stb + OFF_BL + cdst, srcBl + s * 16);
        CP_COMMIT();
    };

    issue(0);
    issue(1);

    const int arow = wm * 64 + (lane & 15);
    const int ach  = lane >> 4;
    const int brow = wn * 32 + ((lane >> 4) & 1) * 8 + (lane & 7);
    const int bch  = (lane >> 3) & 1;

#pragma unroll
    for (int s = 0; s < NSTAGE; ++s) {
        if (s < NSTAGE - 1) { CP_WAIT(1); } else { CP_WAIT(0); }
        __syncthreads();
        if (s + 2 < NSTAGE) issue(s + 2);

        const uint32_t stb = sbase + (uint32_t)(s % 3) * STG;

        uint32_t ah[4][4], bh[4][2], bl[4][2];
#pragma unroll
        for (int i = 0; i < 4; ++i)
            LDSM_X4(ah[i], swz16(stb, arow + i * 16, ach));
#pragma unroll
        for (int jj = 0; jj < 2; ++jj) {
            uint32_t t[4];
            uint32_t ad = swz16(0, brow + jj * 16, bch);
            LDSM_X4(t, stb + OFF_BH + ad);
            bh[2 * jj][0] = t[0]; bh[2 * jj][1] = t[1];
            bh[2 * jj + 1][0] = t[2]; bh[2 * jj + 1][1] = t[3];
            LDSM_X4(t, stb + OFF_BL + ad);
            bl[2 * jj][0] = t[0]; bl[2 * jj][1] = t[1];
            bl[2 * jj + 1][0] = t[2]; bl[2 * jj + 1][1] = t[3];
        }
#pragma unroll
        for (int i = 0; i < 4; ++i)
#pragma unroll
            for (int j = 0; j < 4; ++j) {
                mma16816h(acc[i][j], ah[i], bh[j]);
                mma16816hh(accH[i][j], ah[i], bl[j]);   // lo correction, fp16 acc
            }
    }

    // --- epilogue: acc + f16 correction + bias -> fp16 hi/lo
#pragma unroll
    for (int i = 0; i < 4; ++i) {
        int mb = m0 + wm * 64 + i * 16 + (lane >> 2);
#pragma unroll
        for (int j = 0; j < 4; ++j) {
            int nb = n0 + wn * 32 + j * 8 + (lane & 3) * 2;
            float bx = bias[nb], by = bias[nb + 1];
            __half2 c0 = *reinterpret_cast<__half2*>(&accH[i][j][0]);
            __half2 c1 = *reinterpret_cast<__half2*>(&accH[i][j][1]);
            float v00 = acc[i][j][0] + bx + __low2float(c0);
            float v01 = acc[i][j][1] + by + __high2float(c0);
            float v10 = acc[i][j][2] + bx + __low2float(c1);
            float v11 = acc[i][j][3] + by + __high2float(c1);
            uint32_t hp, lp;
            split2h(v00, v01, hp, lp);
            *(uint32_t*)&Ch[(size_t)mb * Nn + nb] = hp;
            *(uint32_t*)&Cl[(size_t)mb * Nn + nb] = lp;
            split2h(v10, v11, hp, lp);
            *(uint32_t*)&Ch[(size_t)(mb + 8) * Nn + nb] = hp;
            *(uint32_t*)&Cl[(size_t)(mb + 8) * Nn + nb] = lp;
        }
    }
}

// ---------------------------------------------------------------------------
// 1-split fp16 GEMM (v columns, proj): W rounded, 1 fp32-acc MMA.
// ---------------------------------------------------------------------------
template <bool ESPLIT>
__global__ void __launch_bounds__(256, 2)
gemm_1s(const __half* __restrict__ Ah, const __half* __restrict__ Wh,
        const float* __restrict__ bias,
        float* __restrict__ Cf, __half* __restrict__ Ch, __half* __restrict__ Cl,
        int Nn, int nbase)
{
    extern __shared__ char smem[];
    const uint32_t sbase = smem_u32(smem);
    constexpr uint32_t STG = 8192u;
    constexpr uint32_t OFF_BH = 4096u;
    constexpr int NSTAGE = 16;

    const int tid  = threadIdx.x;
    const int lane = tid & 31;
    const int warp = tid >> 5;
    const int m0 = blockIdx.y * 128;
    const int n0 = nbase + blockIdx.x * 128;
    const int wm = warp & 1;
    const int wn = warp >> 1;

    float acc[4][4][4];
#pragma unroll
    for (int i = 0; i < 4; i++)
#pragma unroll
        for (int j = 0; j < 4; j++)
#pragma unroll
            for (int r = 0; r < 4; r++) acc[i][j][r] = 0.f;

    const int crow = tid >> 1;
    const int cch  = tid & 1;
    const uint32_t cdst = swz16(0, crow, cch);
    const __half* srcA  = Ah + (size_t)(m0 + crow) * GK + cch * 8;
    const __half* srcBh = Wh + (size_t)(n0 + crow) * GK + cch * 8;

    auto issue = [&](int s) {
        const uint32_t stb = sbase + (uint32_t)(s % 3) * STG;
        CP_ASYNC16(stb + cdst,          srcA  + s * 16);
        CP_ASYNC16(stb + OFF_BH + cdst, srcBh + s * 16);
        CP_COMMIT();
    };

    issue(0);
    issue(1);

    const int arow = wm * 64 + (lane & 15);
    const int ach  = lane >> 4;
    const int brow = wn * 32 + ((lane >> 4) & 1) * 8 + (lane & 7);
    const int bch  = (lane >> 3) & 1;

#pragma unroll
    for (int s = 0; s < NSTAGE; ++s) {
        if (s < NSTAGE - 1) { CP_WAIT(1); } else { CP_WAIT(0); }
        __syncthreads();
        if (s + 2 < NSTAGE) issue(s + 2);

        const uint32_t stb = sbase + (uint32_t)(s % 3) * STG;

        uint32_t ah[4][4], bh[4][2];
#pragma unroll
        for (int i = 0; i < 4; ++i)
            LDSM_X4(ah[i], swz16(stb, arow + i * 16, ach));
#pragma unroll
        for (int jj = 0; jj < 2; ++jj) {
            uint32_t t[4];
            uint32_t ad = swz16(0, brow + jj * 16, bch);
            LDSM_X4(t, stb + OFF_BH + ad);
            bh[2 * jj][0] = t[0]; bh[2 * jj][1] = t[1];
            bh[2 * jj + 1][0] = t[2]; bh[2 * jj + 1][1] = t[3];
        }
#pragma unroll
        for (int i = 0; i < 4; ++i)
#pragma unroll
            for (int j = 0; j < 4; ++j)
                mma16816h(acc[i][j], ah[i], bh[j]);
    }

#pragma unroll
    for (int i = 0; i < 4; ++i) {
        int mb = m0 + wm * 64 + i * 16 + (lane >> 2);
#pragma unroll
        for (int j = 0; j < 4; ++j) {
            int nb = n0 + wn * 32 + j * 8 + (lane & 3) * 2;
            float bx = bias[nb], by = bias[nb + 1];
            float v00 = acc[i][j][0] + bx, v01 = acc[i][j][1] + by;
            float v10 = acc[i][j][2] + bx, v11 = acc[i][j][3] + by;
            if (ESPLIT) {
                uint32_t hp, lp;
                split2h(v00, v01, hp, lp);
                *(uint32_t*)&Ch[(size_t)mb * Nn + nb] = hp;
                *(uint32_t*)&Cl[(size_t)mb * Nn + nb] = lp;
                split2h(v10, v11, hp, lp);
                *(uint32_t*)&Ch[(size_t)(mb + 8) * Nn + nb] = hp;
                *(uint32_t*)&Cl[(size_t)(mb + 8) * Nn + nb] = lp;
            } else {
                *(float2*)&Cf[(size_t)mb * Nn + nb]       = make_float2(v00, v01);
                *(float2*)&Cf[(size_t)(mb + 8) * Nn + nb] = make_float2(v10, v11);
            }
        }
    }
}

// ---------------------------------------------------------------------------
// Tensor-core attention: S = qh*kh (f32) + qh*kl + ql*kh (f16 acc);
// O = ph*vh (f32) + ph*vl (f16 acc).
// ---------------------------------------------------------------------------
#define ATTN_SMEM (4 * 24576)

__global__ void __launch_bounds__(128)
attn_tc()
{
    extern __shared__ char asmem[];
    const uint32_t sbase = smem_u32(asmem);

    const int tid = threadIdx.x, warp = tid >> 5, lane = tid & 31;
    const int b = blockIdx.x >> 1;
    const int h = (blockIdx.x & 1) * 4 + warp;

    const uint32_t wb = sbase + warp * 24576u;
    const uint32_t Qh = wb, Ql = wb + 4096, Kh = wb + 8192, Kl = wb + 12288,
                   Vh = wb + 16384, Vl = wb + 20480;

    for (int i = lane; i < 112; i += 32) {
        int row = 50 + (i >> 3);
        uint32_t a = row * 64 + (i & 7) * 8;
        STS64(Vh + a, 0u, 0u);
        STS64(Vl + a, 0u, 0u);
    }

    {
        const __half* srcH = g_qkvh + (size_t)b * NTOK * 768 + h * HD;
        const __half* srcL = g_qkvl + (size_t)b * NTOK * 768 + h * HD;
        const uint32_t abase[6] = { Qh, Ql, Kh, Kl, Vh, Vl };
        for (int f = lane; f < 1200; f += 32) {
            int arr = f / 200;
            int g = f - arr * 200;
            int row = g >> 2, c = g & 3;
            int col = (arr >> 1) * 256 + c * 8;
            const __half* s = ((arr & 1) ? srcL : srcH) + (size_t)row * 768 + col;
            CP_ASYNC16(swz(abase[arr], row, c), s);
        }
        CP_COMMIT();
        CP_WAIT(0);
    }
    __syncthreads();

    const float* gbh = g_bias + h * (NTOK * NTOK);
    const int qrow = lane >> 2;
    const int j0l  = (lane & 3) * 2;

#pragma unroll
    for (int half = 0; half < 2; ++half) {
        float    S[2][7][4];
        uint32_t SL[2][7][2];
#pragma unroll
        for (int m = 0; m < 2; m++)
#pragma unroll
            for (int nt = 0; nt < 7; nt++) {
#pragma unroll
                for (int r = 0; r < 4; r++) S[m][nt][r] = 0.f;
                SL[m][nt][0] = 0u; SL[m][nt][1] = 0u;
            }

        // ---- S = Q K^T: hi f32 + lo terms f16 ----
#pragma unroll
        for (int ks = 0; ks < 2; ++ks) {
            uint32_t qh[2][4], ql[2][4];
#pragma unroll
            for (int m = 0; m < 2; ++m) {
                int mt = half * 2 + m;
                int r = mt * 16 + (lane & 15);
                int ch = ks * 2 + (lane >> 4);
                LDSM_X4(qh[m], swz(Qh, r, ch));
                LDSM_X4(ql[m], swz(Ql, r, ch));
            }
#pragma unroll
            for (int nt = 0; nt < 7; ++nt) {
                uint32_t kh[2], kl[2];
                int r = nt * 8 + (lane & 7);
                int ch = ks * 2 + ((lane >> 3) & 1);
                LDSM_X2(kh, swz(Kh, r, ch));
                LDSM_X2(kl, swz(Kl, r, ch));
#pragma unroll
                for (int m = 0; m < 2; ++m) {
                    mma16816h(S[m][nt], qh[m], kh);
                    mma16816hh(SL[m][nt], qh[m], kl);
                    mma16816hh(SL[m][nt], ql[m], kh);
                }
            }
        }
        // fold f16 corrections into S
#pragma unroll
        for (int m = 0; m < 2; ++m)
#pragma unroll
            for (int nt = 0; nt < 7; ++nt) {
                __half2 c0 = *reinterpret_cast<__half2*>(&SL[m][nt][0]);
                __half2 c1 = *reinterpret_cast<__half2*>(&SL[m][nt][1]);
                S[m][nt][0] += __low2float(c0);  S[m][nt][1] += __high2float(c0);
                S[m][nt][2] += __low2float(c1);  S[m][nt][3] += __high2float(c1);
            }

        // ---- bias + mask ----
#pragma unroll
        for (int m = 0; m < 2; ++m) {
            int mt = half * 2 + m;
            int r0 = mt * 16 + qrow, r1 = r0 + 8;
#pragma unroll
            for (int nt = 0; nt < 7; ++nt) {
                int j0 = nt * 8 + j0l;
                if (j0 < NTOK) {
                    if (r0 < NTOK) {
                        float2 bv = *(const float2*)&gbh[r0 * NTOK + j0];
                        S[m][nt][0] += bv.x; S[m][nt][1] += bv.y;
                    }
                    if (r1 < NTOK) {
                        float2 bv = *(const float2*)&gbh[r1 * NTOK + j0];
                        S[m][nt][2] += bv.x; S[m][nt][3] += bv.y;
                    }
                } else {
                    S[m][nt][0] = -1e30f; S[m][nt][2] = -1e30f;
                }
                if (j0 + 1 >= NTOK) { S[m][nt][1] = -1e30f; S[m][nt][3] = -1e30f; }
            }
        }

        // ---- softmax (quad reductions) ----
#pragma unroll
        for (int m = 0; m < 2; ++m) {
            float mx0 = -1e30f, mx1 = -1e30f;
#pragma unroll
            for (int nt = 0; nt < 7; ++nt) {
                mx0 = fmaxf(mx0, fmaxf(S[m][nt][0], S[m][nt][1]));
                mx1 = fmaxf(mx1, fmaxf(S[m][nt][2], S[m][nt][3]));
            }
            mx0 = fmaxf(mx0, __shfl_xor_sync(0xffffffffu, mx0, 1));
            mx0 = fmaxf(mx0, __shfl_xor_sync(0xffffffffu, mx0, 2));
            mx1 = fmaxf(mx1, __shfl_xor_sync(0xffffffffu, mx1, 1));
            mx1 = fmaxf(mx1, __shfl_xor_sync(0xffffffffu, mx1, 2));
            float s0 = 0.f, s1 = 0.f;
#pragma unroll
            for (int nt = 0; nt < 7; ++nt) {
                S[m][nt][0] = __expf(S[m][nt][0] - mx0); s0 += S[m][nt][0];
                S[m][nt][1] = __expf(S[m][nt][1] - mx0); s0 += S[m][nt][1];
                S[m][nt][2] = __expf(S[m][nt][2] - mx1); s1 += S[m][nt][2];
                S[m][nt][3] = __expf(S[m][nt][3] - mx1); s1 += S[m][nt][3];
            }
            s0 += __shfl_xor_sync(0xffffffffu, s0, 1);
            s0 += __shfl_xor_sync(0xffffffffu, s0, 2);
            s1 += __shfl_xor_sync(0xffffffffu, s1, 1);
            s1 += __shfl_xor_sync(0xffffffffu, s1, 2);
            float i0 = 1.f / s0, i1 = 1.f / s1;
#pragma unroll
            for (int nt = 0; nt < 7; ++nt) {
                S[m][nt][0] *= i0; S[m][nt][1] *= i0;
                S[m][nt][2] *= i1; S[m][nt][3] *= i1;
            }
        }

        // ---- O = P V: hi f32 + lo f16 ----
        float    O[2][4][4];
        uint32_t OL[2][4][2];
#pragma unroll
        for (int m = 0; m < 2; m++)
#pragma unroll
            for (int nt = 0; nt < 4; nt++) {
#pragma unroll
                for (int r = 0; r < 4; r++) O[m][nt][r] = 0.f;
                OL[m][nt][0] = 0u; OL[m][nt][1] = 0u;
            }

#pragma unroll
        for (int kt = 0; kt < 4; ++kt) {
            uint32_t vh[2][4], vl[2][4];
#pragma unroll
            for (int np = 0; np < 2; ++np) {
                int r = kt * 16 + (lane & 15);
                int ch = np * 2 + (lane >> 4);
                LDSM_X4_T(vh[np], swz(Vh, r, ch));
                LDSM_X4_T(vl[np], swz(Vl, r, ch));
            }
#pragma unroll
            for (int m = 0; m < 2; ++m) {
                uint32_t ah[4];
                int ntA = 2 * kt, ntB = 2 * kt + 1;
                {
                    __half2 p0 = __floats2half2_rn(S[m][ntA][0], S[m][ntA][1]);
                    __half2 p1 = __floats2half2_rn(S[m][ntA][2], S[m][ntA][3]);
                    ah[0] = *(uint32_t*)&p0; ah[1] = *(uint32_t*)&p1;
                }
                if (ntB < 7) {
                    __half2 p0 = __floats2half2_rn(S[m][ntB][0], S[m][ntB][1]);
                    __half2 p1 = __floats2half2_rn(S[m][ntB][2], S[m][ntB][3]);
                    ah[2] = *(uint32_t*)&p0; ah[3] = *(uint32_t*)&p1;
                } else {
                    ah[2] = ah[3] = 0u;
                }
#pragma unroll
                for (int nt = 0; nt < 4; ++nt) {
                    const uint32_t* bhf = &vh[nt >> 1][(nt & 1) * 2];
                    const uint32_t* blf = &vl[nt >> 1][(nt & 1) * 2];
                    mma16816h(O[m][nt], ah, bhf);
                    mma16816hh(OL[m][nt], ah, blf);
                }
            }
        }

        // ---- store O rows < 50 (add f16 corrections) ----
#pragma unroll
        for (int m = 0; m < 2; ++m) {
            int mt = half * 2 + m;
            int r0 = mt * 16 + qrow, r1 = r0 + 8;
#pragma unroll
            for (int nt = 0; nt < 4; ++nt) {
                int d0 = h * HD + nt * 8 + j0l;
                __half2 c0 = *reinterpret_cast<__half2*>(&OL[m][nt][0]);
                __half2 c1 = *reinterpret_cast<__half2*>(&OL[m][nt][1]);
                if (r0 < NTOK) {
                    __half2 hv = __floats2half2_rn(O[m][nt][0] + __low2float(c0),
                                                   O[m][nt][1] + __high2float(c0));
                    *(uint32_t*)&g_oh[(size_t)(b * NTOK + r0) * CDIM + d0] = *(uint32_t*)&hv;
                }
                if (r1 < NTOK) {
                    __half2 hv = __floats2half2_rn(O[m][nt][2] + __low2float(c1),
                                                   O[m][nt][3] + __high2float(c1));
                    *(uint32_t*)&g_oh[(size_t)(b * NTOK + r1) * CDIM + d0] = *(uint32_t*)&hv;
                }
            }
        }
    }
}

// ---------------------------------------------------------------------------
extern "C" void kernel_launch(void* const* d_in, const int* in_sizes, int n_in,
                              void* d_out, int out_size)
{
    const float* x          = (const float*)d_in[0];
    const float* qkv_w      = (const float*)d_in[1];
    const float* qkv_b      = (const float*)d_in[2];
    const float* proj_w     = (const float*)d_in[3];
    const float* proj_b     = (const float*)d_in[4];
    const float* bias_table = (const float*)d_in[5];
    const int*   rel_idx    = (const int*)d_in[6];
    float* out = (float*)d_out;

    const float scale = 0.17677669529663687f;   // 1/sqrt(32)

    static bool attr_set = false;
    if (!attr_set) {
        cudaFuncSetAttribute(gemm_qk,        cudaFuncAttributeMaxDynamicSharedMemorySize, GEMM_SMEM2);
        cudaFuncSetAttribute(gemm_1s<true>,  cudaFuncAttributeMaxDynamicSharedMemorySize, GEMM_SMEM1);
        cudaFuncSetAttribute(gemm_1s<false>, cudaFuncAttributeMaxDynamicSharedMemorySize, GEMM_SMEM1);
        cudaFuncSetAttribute(attn_tc, cudaFuncAttributeMaxDynamicSharedMemorySize, ATTN_SMEM);
        attr_set = true;
    }

    __half *xh, *wqh, *wql, *wph, *qh, *ql, *oh;
    float *qkvb;
    cudaGetSymbolAddress((void**)&xh,   g_xh);
    cudaGetSymbolAddress((void**)&wqh,  g_wqh);
    cudaGetSymbolAddress((void**)&wql,  g_wql);
    cudaGetSymbolAddress((void**)&wph,  g_wph);
    cudaGetSymbolAddress((void**)&qh,   g_qkvh);
    cudaGetSymbolAddress((void**)&ql,   g_qkvl);
    cudaGetSymbolAddress((void**)&oh,   g_oh);
    cudaGetSymbolAddress((void**)&qkvb, g_qkvb);

    // Launch order keeps the qk GEMM in ncu's capture slot (4th launch).
    conv_bias<<<3, 256>>>(qkv_b, scale);                                        // 1
    conv_w<<<(768 * GK / 4 + 255) / 256, 256>>>(qkv_w, wqh, wql, 768 * GK / 4,
                                                256 * GK / 4, scale);           // 2
    conv_x<<<(MROWS * GK / 4 + 255) / 256, 256>>>(x, xh, MROWS * GK / 4);       // 3

    // 4: q,k columns (N=512), 2-split with f16-acc lo term  <- profiled
    gemm_qk<<<dim3(4, MROWS / 128), 256, GEMM_SMEM2>>>(
        xh, wqh, wql, qkvb, qh, ql, 768);

    bias_expand<<<(NH * NTOK * NTOK + 255) / 256, 256>>>(bias_table, rel_idx);  // 5
    conv_x<<<(CDIM * GK / 4 + 255) / 256, 256>>>(proj_w, wph, CDIM * GK / 4);   // 6

    // 7: v columns (N=256, nbase=512), 1-split
    gemm_1s<true><<<dim3(2, MROWS / 128), 256, GEMM_SMEM1>>>(
        xh, wqh, qkvb, nullptr, qh, ql, 768, 512);

    // 8: attention
    attn_tc<<<BWIN * 2, 128, ATTN_SMEM>>>();

    // 9: proj (N=256), 1-split, fp32 out
    gemm_1s<false><<<dim3(2, MROWS / 128), 256, GEMM_SMEM1>>>(
        oh, wph, proj_b, out, nullptr, nullptr, 256, 0);
}

// round 13
// speedup vs baseline: 1.1041x; 1.1041x over previous
#include <cuda_runtime.h>
#include <cuda_fp16.h>
#include <cstdint>
#include <cstddef>

// ---------------------------------------------------------------------------
// Problem constants
// ---------------------------------------------------------------------------
#define BWIN 2048
#define NTOK 50
#define CDIM 256
#define NH   8
#define HD   32
#define MROWS (BWIN * NTOK)      // 102400
#define GK   256                 // GEMM K

// ---------------------------------------------------------------------------
// Scratch (device globals; no allocation allowed)
// ---------------------------------------------------------------------------
__device__ __half g_xh[(size_t)MROWS * GK];        // x rounded fp16
__device__ __half g_qkvh[(size_t)MROWS * 768];     // qkv hi fp16
__device__ __half g_qkvl[(size_t)MROWS * 768];     // qkv lo fp16
__device__ __half g_oh[(size_t)MROWS * CDIM];      // attention out fp16 (rounded)
__device__ __half g_wqh[768 * GK], g_wql[768 * GK];
__device__ __half g_wph[CDIM * GK];
__device__ float  g_qkvb[768];                     // qkv bias (q-scaled)
__device__ float  g_bias[NH * NTOK * NTOK + 64];   // expanded relpos bias

// ---------------------------------------------------------------------------
// Helpers
// ---------------------------------------------------------------------------
__device__ __forceinline__ uint32_t smem_u32(const void* p) {
    uint32_t a;
    asm("{ .reg .u64 t; cvta.to.shared.u64 t, %1; cvt.u32.u64 %0, t; }" : "=r"(a) : "l"(p));
    return a;
}

// fp32 pair -> packed fp16 hi pair + packed fp16 lo pair
__device__ __forceinline__ void split2h(float x, float y, uint32_t& hp, uint32_t& lp) {
    __half2 h = __floats2half2_rn(x, y);
    hp = *reinterpret_cast<uint32_t*>(&h);
    float rx = x - __low2float(h);
    float ry = y - __high2float(h);
    __half2 l = __floats2half2_rn(rx, ry);
    lp = *reinterpret_cast<uint32_t*>(&l);
}

#define LDSM_X4(r, a) asm volatile( \
    "ldmatrix.sync.aligned.m8n8.x4.shared.b16 {%0,%1,%2,%3}, [%4];" \
    : "=r"((r)[0]), "=r"((r)[1]), "=r"((r)[2]), "=r"((r)[3]) : "r"(a))
#define LDSM_X2(r, a) asm volatile( \
    "ldmatrix.sync.aligned.m8n8.x2.shared.b16 {%0,%1}, [%2];" \
    : "=r"((r)[0]), "=r"((r)[1]) : "r"(a))
#define LDSM_X4_T(r, a) asm volatile( \
    "ldmatrix.sync.aligned.m8n8.x4.trans.shared.b16 {%0,%1,%2,%3}, [%4];" \
    : "=r"((r)[0]), "=r"((r)[1]), "=r"((r)[2]), "=r"((r)[3]) : "r"(a))

__device__ __forceinline__ void mma16816h(float* d, const uint32_t* a, const uint32_t* b) {
    asm volatile(
        "mma.sync.aligned.m16n8k16.row.col.f32.f16.f16.f32 "
        "{%0,%1,%2,%3},{%4,%5,%6,%7},{%8,%9},{%0,%1,%2,%3};"
        : "+f"(d[0]), "+f"(d[1]), "+f"(d[2]), "+f"(d[3])
        : "r"(a[0]), "r"(a[1]), "r"(a[2]), "r"(a[3]), "r"(b[0]), "r"(b[1]));
}

#define CP_ASYNC16(dst, src) asm volatile( \
    "cp.async.cg.shared.global [%0], [%1], 16;" :: "r"(dst), "l"(src))
#define CP_COMMIT() asm volatile("cp.async.commit_group;" ::: "memory")
#define CP_WAIT(n)  asm volatile("cp.async.wait_group %0;" :: "n"(n) : "memory")
#define STS64(a, x, y) asm volatile("st.shared.v2.b32 [%0], {%1,%2};" :: "r"(a), "r"(x), "r"(y) : "memory")

// 64B-row swizzle (attention tiles)
__device__ __forceinline__ uint32_t swz(uint32_t base, int r, int ch) {
    return base + r * 64 + 16 * (ch ^ ((r >> 1) & 3));
}
// 32B-row swizzle (GEMM k16 stages)
__device__ __forceinline__ uint32_t swz16(uint32_t base, int r, int ch) {
    return base + r * 32 + 16 * (ch ^ ((r >> 2) & 1));
}

// ---------------------------------------------------------------------------
// x converter (large, separate)
// ---------------------------------------------------------------------------
__global__ void conv_x(const float* __restrict__ src, __half* __restrict__ dh, int n4)
{
    int i = blockIdx.x * 256 + threadIdx.x;
    if (i >= n4) return;
    float4 v = ((const float4*)src)[i];
    __half2 h01 = __floats2half2_rn(v.x, v.y);
    __half2 h23 = __floats2half2_rn(v.z, v.w);
    ((uint2*)dh)[i] = make_uint2(*(uint32_t*)&h01, *(uint32_t*)&h23);
}

// ---------------------------------------------------------------------------
// Fused prep: qkv-w split (+q scale), proj-w round, bias expand, qkv bias.
// Segments: [0, 49152) qkv w | [.., +16384) proj w | [.., +20000) bias | [.., +768) qkvb
// ---------------------------------------------------------------------------
#define SEG0 49152
#define SEG1 (SEG0 + 16384)
#define SEG2 (SEG1 + 20000)
#define SEG3 (SEG2 + 768)

__global__ void prep_all(const float* __restrict__ qkv_w,
                         const float* __restrict__ proj_w,
                         const float* __restrict__ bt,
                         const int*   __restrict__ ri,
                         const float* __restrict__ qkv_b,
                         float scale)
{
    int idx = blockIdx.x * 256 + threadIdx.x;
    if (idx < SEG0) {
        // qkv weight split; first 16384 float4s (q rows) scaled
        float4 v = ((const float4*)qkv_w)[idx];
        if (idx < 16384) { v.x *= scale; v.y *= scale; v.z *= scale; v.w *= scale; }
        uint32_t h01, l01, h23, l23;
        split2h(v.x, v.y, h01, l01);
        split2h(v.z, v.w, h23, l23);
        ((uint2*)g_wqh)[idx] = make_uint2(h01, h23);
        ((uint2*)g_wql)[idx] = make_uint2(l01, l23);
    } else if (idx < SEG1) {
        int i = idx - SEG0;
        float4 v = ((const float4*)proj_w)[i];
        __half2 h01 = __floats2half2_rn(v.x, v.y);
        __half2 h23 = __floats2half2_rn(v.z, v.w);
        ((uint2*)g_wph)[i] = make_uint2(*(uint32_t*)&h01, *(uint32_t*)&h23);
    } else if (idx < SEG2) {
        int i = idx - SEG1;
        int h = i / (NTOK * NTOK);
        int rem = i - h * NTOK * NTOK;
        int r = rem / NTOK, c = rem - r * NTOK;
        float v = 0.f;
        if (r > 0 && c > 0) v = bt[ri[(r - 1) * 49 + (c - 1)] * NH + h];
        g_bias[i] = v;
    } else if (idx < SEG3) {
        int i = idx - SEG2;
        g_qkvb[i] = qkv_b[i] * (i < 256 ? scale : 1.f);
    }
}

// ---------------------------------------------------------------------------
// Merged QKV GEMM: grid (6, 800). Cols 0..511 (qk): W 2-split, 2 MMAs.
// Cols 512..767 (v): W rounded (hi only), 1 MMA. Runtime-uniform branch.
// 256 threads, 8 warps (2x4), warp tile 64x32, k16 x 3-stage ring, 2 CTAs/SM.
// ---------------------------------------------------------------------------
#define GEMM_SMEM2 (3 * 12288)
#define GEMM_SMEM1 (3 * 8192)

__global__ void __launch_bounds__(256, 2)
gemm_qkv(const __half* __restrict__ Ah,
         const __half* __restrict__ Wh, const __half* __restrict__ Wl,
         const float* __restrict__ bias,
         __half* __restrict__ Ch, __half* __restrict__ Cl)
{
    extern __shared__ char smem[];
    const uint32_t sbase = smem_u32(smem);
    constexpr uint32_t STG = 12288u;
    constexpr uint32_t OFF_BH = 4096u, OFF_BL = 8192u;
    constexpr int NSTAGE = 16;
    constexpr int Nn = 768;

    const bool twosplit = (blockIdx.x < 4);   // uniform per CTA
    const int tid  = threadIdx.x;
    const int lane = tid & 31;
    const int warp = tid >> 5;
    const int m0 = blockIdx.y * 128;
    const int n0 = blockIdx.x * 128;
    const int wm = warp & 1;
    const int wn = warp >> 1;

    float acc[4][4][4];
#pragma unroll
    for (int i = 0; i < 4; i++)
#pragma unroll
        for (int j = 0; j < 4; j++)
#pragma unroll
            for (int r = 0; r < 4; r++) acc[i][j][r] = 0.f;

    const int crow = tid >> 1;
    const int cch  = tid & 1;
    const uint32_t cdst = swz16(0, crow, cch);
    const __half* srcA  = Ah + (size_t)(m0 + crow) * GK + cch * 8;
    const __half* srcBh = Wh + (size_t)(n0 + crow) * GK + cch * 8;
    const __half* srcBl = Wl + (size_t)(n0 + crow) * GK + cch * 8;

    auto issue = [&](int s) {
        const uint32_t stb = sbase + (uint32_t)(s % 3) * STG;
        CP_ASYNC16(stb + cdst,          srcA  + s * 16);
        CP_ASYNC16(stb + OFF_BH + cdst, srcBh + s * 16);
        if (twosplit) CP_ASYNC16(stb + OFF_BL + cdst, srcBl + s * 16);
        CP_COMMIT();
    };

    issue(0);
    issue(1);

    const int arow = wm * 64 + (lane & 15);
    const int ach  = lane >> 4;
    const int brow = wn * 32 + ((lane >> 4) & 1) * 8 + (lane & 7);
    const int bch  = (lane >> 3) & 1;

#pragma unroll
    for (int s = 0; s < NSTAGE; ++s) {
        if (s < NSTAGE - 1) { CP_WAIT(1); } else { CP_WAIT(0); }
        __syncthreads();
        if (s + 2 < NSTAGE) issue(s + 2);

        const uint32_t stb = sbase + (uint32_t)(s % 3) * STG;

        uint32_t ah[4][4], bh[4][2], bl[4][2];
#pragma unroll
        for (int i = 0; i < 4; ++i)
            LDSM_X4(ah[i], swz16(stb, arow + i * 16, ach));
#pragma unroll
        for (int jj = 0; jj < 2; ++jj) {
            uint32_t t[4];
            uint32_t ad = swz16(0, brow + jj * 16, bch);
            LDSM_X4(t, stb + OFF_BH + ad);
            bh[2 * jj][0] = t[0]; bh[2 * jj][1] = t[1];
            bh[2 * jj + 1][0] = t[2]; bh[2 * jj + 1][1] = t[3];
            if (twosplit) {
                LDSM_X4(t, stb + OFF_BL + ad);
                bl[2 * jj][0] = t[0]; bl[2 * jj][1] = t[1];
                bl[2 * jj + 1][0] = t[2]; bl[2 * jj + 1][1] = t[3];
            }
        }
        if (twosplit) {
#pragma unroll
            for (int i = 0; i < 4; ++i)
#pragma unroll
                for (int j = 0; j < 4; ++j) {
                    mma16816h(acc[i][j], ah[i], bh[j]);
                    mma16816h(acc[i][j], ah[i], bl[j]);
                }
        } else {
#pragma unroll
            for (int i = 0; i < 4; ++i)
#pragma unroll
                for (int j = 0; j < 4; ++j)
                    mma16816h(acc[i][j], ah[i], bh[j]);
        }
    }

    // --- epilogue: +bias -> fp16 hi/lo
#pragma unroll
    for (int i = 0; i < 4; ++i) {
        int mb = m0 + wm * 64 + i * 16 + (lane >> 2);
#pragma unroll
        for (int j = 0; j < 4; ++j) {
            int nb = n0 + wn * 32 + j * 8 + (lane & 3) * 2;
            float bx = bias[nb], by = bias[nb + 1];
            float v00 = acc[i][j][0] + bx, v01 = acc[i][j][1] + by;
            float v10 = acc[i][j][2] + bx, v11 = acc[i][j][3] + by;
            uint32_t hp, lp;
            split2h(v00, v01, hp, lp);
            *(uint32_t*)&Ch[(size_t)mb * Nn + nb] = hp;
            *(uint32_t*)&Cl[(size_t)mb * Nn + nb] = lp;
            split2h(v10, v11, hp, lp);
            *(uint32_t*)&Ch[(size_t)(mb + 8) * Nn + nb] = hp;
            *(uint32_t*)&Cl[(size_t)(mb + 8) * Nn + nb] = lp;
        }
    }
}

// ---------------------------------------------------------------------------
// Proj GEMM: 1-split, fp32 out. Same engine.
// ---------------------------------------------------------------------------
__global__ void __launch_bounds__(256, 2)
gemm_proj(const __half* __restrict__ Ah, const __half* __restrict__ Wh,
          const float* __restrict__ bias, float* __restrict__ Cf)
{
    extern __shared__ char smem[];
    const uint32_t sbase = smem_u32(smem);
    constexpr uint32_t STG = 8192u;
    constexpr uint32_t OFF_BH = 4096u;
    constexpr int NSTAGE = 16;
    constexpr int Nn = 256;

    const int tid  = threadIdx.x;
    const int lane = tid & 31;
    const int warp = tid >> 5;
    const int m0 = blockIdx.y * 128;
    const int n0 = blockIdx.x * 128;
    const int wm = warp & 1;
    const int wn = warp >> 1;

    float acc[4][4][4];
#pragma unroll
    for (int i = 0; i < 4; i++)
#pragma unroll
        for (int j = 0; j < 4; j++)
#pragma unroll
            for (int r = 0; r < 4; r++) acc[i][j][r] = 0.f;

    const int crow = tid >> 1;
    const int cch  = tid & 1;
    const uint32_t cdst = swz16(0, crow, cch);
    const __half* srcA  = Ah + (size_t)(m0 + crow) * GK + cch * 8;
    const __half* srcBh = Wh + (size_t)(n0 + crow) * GK + cch * 8;

    auto issue = [&](int s) {
        const uint32_t stb = sbase + (uint32_t)(s % 3) * STG;
        CP_ASYNC16(stb + cdst,          srcA  + s * 16);
        CP_ASYNC16(stb + OFF_BH + cdst, srcBh + s * 16);
        CP_COMMIT();
    };

    issue(0);
    issue(1);

    const int arow = wm * 64 + (lane & 15);
    const int ach  = lane >> 4;
    const int brow = wn * 32 + ((lane >> 4) & 1) * 8 + (lane & 7);
    const int bch  = (lane >> 3) & 1;

#pragma unroll
    for (int s = 0; s < NSTAGE; ++s) {
        if (s < NSTAGE - 1) { CP_WAIT(1); } else { CP_WAIT(0); }
        __syncthreads();
        if (s + 2 < NSTAGE) issue(s + 2);

        const uint32_t stb = sbase + (uint32_t)(s % 3) * STG;

        uint32_t ah[4][4], bh[4][2];
#pragma unroll
        for (int i = 0; i < 4; ++i)
            LDSM_X4(ah[i], swz16(stb, arow + i * 16, ach));
#pragma unroll
        for (int jj = 0; jj < 2; ++jj) {
            uint32_t t[4];
            uint32_t ad = swz16(0, brow + jj * 16, bch);
            LDSM_X4(t, stb + OFF_BH + ad);
            bh[2 * jj][0] = t[0]; bh[2 * jj][1] = t[1];
            bh[2 * jj + 1][0] = t[2]; bh[2 * jj + 1][1] = t[3];
        }
#pragma unroll
        for (int i = 0; i < 4; ++i)
#pragma unroll
            for (int j = 0; j < 4; ++j)
                mma16816h(acc[i][j], ah[i], bh[j]);
    }

#pragma unroll
    for (int i = 0; i < 4; ++i) {
        int mb = m0 + wm * 64 + i * 16 + (lane >> 2);
#pragma unroll
        for (int j = 0; j < 4; ++j) {
            int nb = n0 + wn * 32 + j * 8 + (lane & 3) * 2;
            float bx = bias[nb], by = bias[nb + 1];
            *(float2*)&Cf[(size_t)mb * Nn + nb] =
                make_float2(acc[i][j][0] + bx, acc[i][j][1] + by);
            *(float2*)&Cf[(size_t)(mb + 8) * Nn + nb] =
                make_float2(acc[i][j][2] + bx, acc[i][j][3] + by);
        }
    }
}

// ---------------------------------------------------------------------------
// Tensor-core attention (R10 version, all fp32-acc):
// S = QK^T 3-MMA split; O = P V 2-MMA (ph*vh + ph*vl).
// ---------------------------------------------------------------------------
#define ATTN_SMEM (4 * 24576)

__global__ void __launch_bounds__(128)
attn_tc()
{
    extern __shared__ char asmem[];
    const uint32_t sbase = smem_u32(asmem);

    const int tid = threadIdx.x, warp = tid >> 5, lane = tid & 31;
    const int b = blockIdx.x >> 1;
    const int h = (blockIdx.x & 1) * 4 + warp;

    const uint32_t wb = sbase + warp * 24576u;
    const uint32_t Qh = wb, Ql = wb + 4096, Kh = wb + 8192, Kl = wb + 12288,
                   Vh = wb + 16384, Vl = wb + 20480;

    for (int i = lane; i < 112; i += 32) {
        int row = 50 + (i >> 3);
        uint32_t a = row * 64 + (i & 7) * 8;
        STS64(Vh + a, 0u, 0u);
        STS64(Vl + a, 0u, 0u);
    }

    {
        const __half* srcH = g_qkvh + (size_t)b * NTOK * 768 + h * HD;
        const __half* srcL = g_qkvl + (size_t)b * NTOK * 768 + h * HD;
        const uint32_t abase[6] = { Qh, Ql, Kh, Kl, Vh, Vl };
        for (int f = lane; f < 1200; f += 32) {
            int arr = f / 200;
            int g = f - arr * 200;
            int row = g >> 2, c = g & 3;
            int col = (arr >> 1) * 256 + c * 8;
            const __half* s = ((arr & 1) ? srcL : srcH) + (size_t)row * 768 + col;
            CP_ASYNC16(swz(abase[arr], row, c), s);
        }
        CP_COMMIT();
        CP_WAIT(0);
    }
    __syncwarp();

    const float* gbh = g_bias + h * (NTOK * NTOK);
    const int qrow = lane >> 2;
    const int j0l  = (lane & 3) * 2;

#pragma unroll
    for (int half = 0; half < 2; ++half) {
        float S[2][7][4];
#pragma unroll
        for (int m = 0; m < 2; m++)
#pragma unroll
            for (int nt = 0; nt < 7; nt++)
#pragma unroll
                for (int r = 0; r < 4; r++) S[m][nt][r] = 0.f;

#pragma unroll
        for (int ks = 0; ks < 2; ++ks) {
            uint32_t qh[2][4], ql[2][4];
#pragma unroll
            for (int m = 0; m < 2; ++m) {
                int mt = half * 2 + m;
                int r = mt * 16 + (lane & 15);
                int ch = ks * 2 + (lane >> 4);
                LDSM_X4(qh[m], swz(Qh, r, ch));
                LDSM_X4(ql[m], swz(Ql, r, ch));
            }
#pragma unroll
            for (int nt = 0; nt < 7; ++nt) {
                uint32_t kh[2], kl[2];
                int r = nt * 8 + (lane & 7);
                int ch = ks * 2 + ((lane >> 3) & 1);
                LDSM_X2(kh, swz(Kh, r, ch));
                LDSM_X2(kl, swz(Kl, r, ch));
#pragma unroll
                for (int m = 0; m < 2; ++m) {
                    mma16816h(S[m][nt], qh[m], kh);
                    mma16816h(S[m][nt], qh[m], kl);
                    mma16816h(S[m][nt], ql[m], kh);
                }
            }
        }

#pragma unroll
        for (int m = 0; m < 2; ++m) {
            int mt = half * 2 + m;
            int r0 = mt * 16 + qrow, r1 = r0 + 8;
#pragma unroll
            for (int nt = 0; nt < 7; ++nt) {
                int j0 = nt * 8 + j0l;
                if (j0 < NTOK) {
                    if (r0 < NTOK) {
                        float2 bv = *(const float2*)&gbh[r0 * NTOK + j0];
                        S[m][nt][0] += bv.x; S[m][nt][1] += bv.y;
                    }
                    if (r1 < NTOK) {
                        float2 bv = *(const float2*)&gbh[r1 * NTOK + j0];
                        S[m][nt][2] += bv.x; S[m][nt][3] += bv.y;
                    }
                } else {
                    S[m][nt][0] = -1e30f; S[m][nt][2] = -1e30f;
                }
                if (j0 + 1 >= NTOK) { S[m][nt][1] = -1e30f; S[m][nt][3] = -1e30f; }
            }
        }

#pragma unroll
        for (int m = 0; m < 2; ++m) {
            float mx0 = -1e30f, mx1 = -1e30f;
#pragma unroll
            for (int nt = 0; nt < 7; ++nt) {
                mx0 = fmaxf(mx0, fmaxf(S[m][nt][0], S[m][nt][1]));
                mx1 = fmaxf(mx1, fmaxf(S[m][nt][2], S[m][nt][3]));
            }
            mx0 = fmaxf(mx0, __shfl_xor_sync(0xffffffffu, mx0, 1));
            mx0 = fmaxf(mx0, __shfl_xor_sync(0xffffffffu, mx0, 2));
            mx1 = fmaxf(mx1, __shfl_xor_sync(0xffffffffu, mx1, 1));
            mx1 = fmaxf(mx1, __shfl_xor_sync(0xffffffffu, mx1, 2));
            float s0 = 0.f, s1 = 0.f;
#pragma unroll
            for (int nt = 0; nt < 7; ++nt) {
                S[m][nt][0] = __expf(S[m][nt][0] - mx0); s0 += S[m][nt][0];
                S[m][nt][1] = __expf(S[m][nt][1] - mx0); s0 += S[m][nt][1];
                S[m][nt][2] = __expf(S[m][nt][2] - mx1); s1 += S[m][nt][2];
                S[m][nt][3] = __expf(S[m][nt][3] - mx1); s1 += S[m][nt][3];
            }
            s0 += __shfl_xor_sync(0xffffffffu, s0, 1);
            s0 += __shfl_xor_sync(0xffffffffu, s0, 2);
            s1 += __shfl_xor_sync(0xffffffffu, s1, 1);
            s1 += __shfl_xor_sync(0xffffffffu, s1, 2);
            float i0 = 1.f / s0, i1 = 1.f / s1;
#pragma unroll
            for (int nt = 0; nt < 7; ++nt) {
                S[m][nt][0] *= i0; S[m][nt][1] *= i0;
                S[m][nt][2] *= i1; S[m][nt][3] *= i1;
            }
        }

        float O[2][4][4];
#pragma unroll
        for (int m = 0; m < 2; m++)
#pragma unroll
            for (int nt = 0; nt < 4; nt++)
#pragma unroll
                for (int r = 0; r < 4; r++) O[m][nt][r] = 0.f;

#pragma unroll
        for (int kt = 0; kt < 4; ++kt) {
            uint32_t vh[2][4], vl[2][4];
#pragma unroll
            for (int np = 0; np < 2; ++np) {
                int r = kt * 16 + (lane & 15);
                int ch = np * 2 + (lane >> 4);
                LDSM_X4_T(vh[np], swz(Vh, r, ch));
                LDSM_X4_T(vl[np], swz(Vl, r, ch));
            }
#pragma unroll
            for (int m = 0; m < 2; ++m) {
                uint32_t ah[4];
                int ntA = 2 * kt, ntB = 2 * kt + 1;
                {
                    __half2 p0 = __floats2half2_rn(S[m][ntA][0], S[m][ntA][1]);
                    __half2 p1 = __floats2half2_rn(S[m][ntA][2], S[m][ntA][3]);
                    ah[0] = *(uint32_t*)&p0; ah[1] = *(uint32_t*)&p1;
                }
                if (ntB < 7) {
                    __half2 p0 = __floats2half2_rn(S[m][ntB][0], S[m][ntB][1]);
                    __half2 p1 = __floats2half2_rn(S[m][ntB][2], S[m][ntB][3]);
                    ah[2] = *(uint32_t*)&p0; ah[3] = *(uint32_t*)&p1;
                } else {
                    ah[2] = ah[3] = 0u;
                }
#pragma unroll
                for (int nt = 0; nt < 4; ++nt) {
                    const uint32_t* bhf = &vh[nt >> 1][(nt & 1) * 2];
                    const uint32_t* blf = &vl[nt >> 1][(nt & 1) * 2];
                    mma16816h(O[m][nt], ah, bhf);
                    mma16816h(O[m][nt], ah, blf);
                }
            }
        }

#pragma unroll
        for (int m = 0; m < 2; ++m) {
            int mt = half * 2 + m;
            int r0 = mt * 16 + qrow, r1 = r0 + 8;
#pragma unroll
            for (int nt = 0; nt < 4; ++nt) {
                int d0 = h * HD + nt * 8 + j0l;
                if (r0 < NTOK) {
                    __half2 hv = __floats2half2_rn(O[m][nt][0], O[m][nt][1]);
                    *(uint32_t*)&g_oh[(size_t)(b * NTOK + r0) * CDIM + d0] = *(uint32_t*)&hv;
                }
                if (r1 < NTOK) {
                    __half2 hv = __floats2half2_rn(O[m][nt][2], O[m][nt][3]);
                    *(uint32_t*)&g_oh[(size_t)(b * NTOK + r1) * CDIM + d0] = *(uint32_t*)&hv;
                }
            }
        }
    }
}

// ---------------------------------------------------------------------------
extern "C" void kernel_launch(void* const* d_in, const int* in_sizes, int n_in,
                              void* d_out, int out_size)
{
    const float* x          = (const float*)d_in[0];
    const float* qkv_w      = (const float*)d_in[1];
    const float* qkv_b      = (const float*)d_in[2];
    const float* proj_w     = (const float*)d_in[3];
    const float* proj_b     = (const float*)d_in[4];
    const float* bias_table = (const float*)d_in[5];
    const int*   rel_idx    = (const int*)d_in[6];
    float* out = (float*)d_out;

    const float scale = 0.17677669529663687f;   // 1/sqrt(32)

    static bool attr_set = false;
    if (!attr_set) {
        cudaFuncSetAttribute(gemm_qkv,  cudaFuncAttributeMaxDynamicSharedMemorySize, GEMM_SMEM2);
        cudaFuncSetAttribute(gemm_proj, cudaFuncAttributeMaxDynamicSharedMemorySize, GEMM_SMEM1);
        cudaFuncSetAttribute(attn_tc,   cudaFuncAttributeMaxDynamicSharedMemorySize, ATTN_SMEM);
        attr_set = true;
    }

    __half *xh, *wqh, *wql, *wph, *qh, *ql, *oh;
    float *qkvb;
    cudaGetSymbolAddress((void**)&xh,   g_xh);
    cudaGetSymbolAddress((void**)&wqh,  g_wqh);
    cudaGetSymbolAddress((void**)&wql,  g_wql);
    cudaGetSymbolAddress((void**)&wph,  g_wph);
    cudaGetSymbolAddress((void**)&qh,   g_qkvh);
    cudaGetSymbolAddress((void**)&ql,   g_qkvl);
    cudaGetSymbolAddress((void**)&oh,   g_oh);
    cudaGetSymbolAddress((void**)&qkvb, g_qkvb);

    // 1: fused prep (weights, bias table, bias)
    prep_all<<<(SEG3 + 255) / 256, 256>>>(qkv_w, proj_w, bias_table, rel_idx, qkv_b, scale);
    // 2: x conversion
    conv_x<<<(MROWS * GK / 4 + 255) / 256, 256>>>(x, xh, MROWS * GK / 4);
    // 3: merged QKV (qk 2-split, v 1-split)
    gemm_qkv<<<dim3(6, MROWS / 128), 256, GEMM_SMEM2>>>(xh, wqh, wql, qkvb, qh, ql);
    // 4: attention  <- profiled launch
    attn_tc<<<BWIN * 2, 128, ATTN_SMEM>>>();
    // 5: proj
    gemm_proj<<<dim3(2, MROWS / 128), 256, GEMM_SMEM1>>>(oh, wph, proj_b, out);
}

// round 15
// speedup vs baseline: 1.2106x; 1.0965x over previous
#include <cuda_runtime.h>
#include <cuda_fp16.h>
#include <cstdint>
#include <cstddef>

// ---------------------------------------------------------------------------
// Problem constants
// ---------------------------------------------------------------------------
#define BWIN 2048
#define NTOK 50
#define CDIM 256
#define NH   8
#define HD   32
#define MROWS (BWIN * NTOK)      // 102400
#define GK   256                 // GEMM K

// ---------------------------------------------------------------------------
// Scratch (device globals; no allocation allowed)
// ---------------------------------------------------------------------------
__device__ __half g_xh[(size_t)MROWS * GK];        // x rounded fp16
__device__ __half g_qkvh[(size_t)MROWS * 768];     // qkv hi fp16 (v: rounded)
__device__ __half g_qkvl[(size_t)MROWS * 768];     // qkv lo fp16 (q,k only)
__device__ __half g_oh[(size_t)MROWS * CDIM];      // attention out fp16 (rounded)
__device__ __half g_wqh[768 * GK], g_wql[768 * GK];
__device__ __half g_wph[CDIM * GK];
__device__ float  g_qkvb[768];                     // qkv bias (q-scaled)
__device__ float  g_bias[NH * NTOK * NTOK + 64];   // expanded relpos bias

// ---------------------------------------------------------------------------
// Helpers
// ---------------------------------------------------------------------------
__device__ __forceinline__ uint32_t smem_u32(const void* p) {
    uint32_t a;
    asm("{ .reg .u64 t; cvta.to.shared.u64 t, %1; cvt.u32.u64 %0, t; }" : "=r"(a) : "l"(p));
    return a;
}

__device__ __forceinline__ void split2h(float x, float y, uint32_t& hp, uint32_t& lp) {
    __half2 h = __floats2half2_rn(x, y);
    hp = *reinterpret_cast<uint32_t*>(&h);
    float rx = x - __low2float(h);
    float ry = y - __high2float(h);
    __half2 l = __floats2half2_rn(rx, ry);
    lp = *reinterpret_cast<uint32_t*>(&l);
}

#define LDSM_X4(r, a) asm volatile( \
    "ldmatrix.sync.aligned.m8n8.x4.shared.b16 {%0,%1,%2,%3}, [%4];" \
    : "=r"((r)[0]), "=r"((r)[1]), "=r"((r)[2]), "=r"((r)[3]) : "r"(a))
#define LDSM_X2(r, a) asm volatile( \
    "ldmatrix.sync.aligned.m8n8.x2.shared.b16 {%0,%1}, [%2];" \
    : "=r"((r)[0]), "=r"((r)[1]) : "r"(a))
#define LDSM_X4_T(r, a) asm volatile( \
    "ldmatrix.sync.aligned.m8n8.x4.trans.shared.b16 {%0,%1,%2,%3}, [%4];" \
    : "=r"((r)[0]), "=r"((r)[1]), "=r"((r)[2]), "=r"((r)[3]) : "r"(a))

__device__ __forceinline__ void mma16816h(float* d, const uint32_t* a, const uint32_t* b) {
    asm volatile(
        "mma.sync.aligned.m16n8k16.row.col.f32.f16.f16.f32 "
        "{%0,%1,%2,%3},{%4,%5,%6,%7},{%8,%9},{%0,%1,%2,%3};"
        : "+f"(d[0]), "+f"(d[1]), "+f"(d[2]), "+f"(d[3])
        : "r"(a[0]), "r"(a[1]), "r"(a[2]), "r"(a[3]), "r"(b[0]), "r"(b[1]));
}

#define CP_ASYNC16(dst, src) asm volatile( \
    "cp.async.cg.shared.global [%0], [%1], 16;" :: "r"(dst), "l"(src))
#define CP_COMMIT() asm volatile("cp.async.commit_group;" ::: "memory")
#define CP_WAIT(n)  asm volatile("cp.async.wait_group %0;" :: "n"(n) : "memory")
#define STS64(a, x, y) asm volatile("st.shared.v2.b32 [%0], {%1,%2};" :: "r"(a), "r"(x), "r"(y) : "memory")

// 64B-row swizzle (attention tiles)
__device__ __forceinline__ uint32_t swz(uint32_t base, int r, int ch) {
    return base + r * 64 + 16 * (ch ^ ((r >> 1) & 3));
}
// 32B-row swizzle (GEMM k16 stages)
__device__ __forceinline__ uint32_t swz16(uint32_t base, int r, int ch) {
    return base + r * 32 + 16 * (ch ^ ((r >> 2) & 1));
}

// ---------------------------------------------------------------------------
// x converter
// ---------------------------------------------------------------------------
__global__ void conv_x(const float* __restrict__ src, __half* __restrict__ dh, int n4)
{
    int i = blockIdx.x * 256 + threadIdx.x;
    if (i >= n4) return;
    float4 v = ((const float4*)src)[i];
    __half2 h01 = __floats2half2_rn(v.x, v.y);
    __half2 h23 = __floats2half2_rn(v.z, v.w);
    ((uint2*)dh)[i] = make_uint2(*(uint32_t*)&h01, *(uint32_t*)&h23);
}

// ---------------------------------------------------------------------------
// Fused prep
// ---------------------------------------------------------------------------
#define SEG0 49152
#define SEG1 (SEG0 + 16384)
#define SEG2 (SEG1 + 20000)
#define SEG3 (SEG2 + 768)

__global__ void prep_all(const float* __restrict__ qkv_w,
                         const float* __restrict__ proj_w,
                         const float* __restrict__ bt,
                         const int*   __restrict__ ri,
                         const float* __restrict__ qkv_b,
                         float scale)
{
    int idx = blockIdx.x * 256 + threadIdx.x;
    if (idx < SEG0) {
        float4 v = ((const float4*)qkv_w)[idx];
        if (idx < 16384) { v.x *= scale; v.y *= scale; v.z *= scale; v.w *= scale; }
        uint32_t h01, l01, h23, l23;
        split2h(v.x, v.y, h01, l01);
        split2h(v.z, v.w, h23, l23);
        ((uint2*)g_wqh)[idx] = make_uint2(h01, h23);
        ((uint2*)g_wql)[idx] = make_uint2(l01, l23);
    } else if (idx < SEG1) {
        int i = idx - SEG0;
        float4 v = ((const float4*)proj_w)[i];
        __half2 h01 = __floats2half2_rn(v.x, v.y);
        __half2 h23 = __floats2half2_rn(v.z, v.w);
        ((uint2*)g_wph)[i] = make_uint2(*(uint32_t*)&h01, *(uint32_t*)&h23);
    } else if (idx < SEG2) {
        int i = idx - SEG1;
        int h = i / (NTOK * NTOK);
        int rem = i - h * NTOK * NTOK;
        int r = rem / NTOK, c = rem - r * NTOK;
        float v = 0.f;
        if (r > 0 && c > 0) v = bt[ri[(r - 1) * 49 + (c - 1)] * NH + h];
        g_bias[i] = v;
    } else if (idx < SEG3) {
        int i = idx - SEG2;
        g_qkvb[i] = qkv_b[i] * (i < 256 ? scale : 1.f);
    }
}

// ---------------------------------------------------------------------------
// Merged QKV GEMM: cols 0..511 (qk) 2-split hi/lo out; cols 512..767 (v)
// 1-split, ROUNDED single fp16 out (no lo write).
// ---------------------------------------------------------------------------
#define GEMM_SMEM2 (3 * 12288)
#define GEMM_SMEM1 (3 * 8192)

__global__ void __launch_bounds__(256, 2)
gemm_qkv(const __half* __restrict__ Ah,
         const __half* __restrict__ Wh, const __half* __restrict__ Wl,
         const float* __restrict__ bias,
         __half* __restrict__ Ch, __half* __restrict__ Cl)
{
    extern __shared__ char smem[];
    const uint32_t sbase = smem_u32(smem);
    constexpr uint32_t STG = 12288u;
    constexpr uint32_t OFF_BH = 4096u, OFF_BL = 8192u;
    constexpr int NSTAGE = 16;
    constexpr int Nn = 768;

    const bool twosplit = (blockIdx.x < 4);
    const int tid  = threadIdx.x;
    const int lane = tid & 31;
    const int warp = tid >> 5;
    const int m0 = blockIdx.y * 128;
    const int n0 = blockIdx.x * 128;
    const int wm = warp & 1;
    const int wn = warp >> 1;

    float acc[4][4][4];
#pragma unroll
    for (int i = 0; i < 4; i++)
#pragma unroll
        for (int j = 0; j < 4; j++)
#pragma unroll
            for (int r = 0; r < 4; r++) acc[i][j][r] = 0.f;

    const int crow = tid >> 1;
    const int cch  = tid & 1;
    const uint32_t cdst = swz16(0, crow, cch);
    const __half* srcA  = Ah + (size_t)(m0 + crow) * GK + cch * 8;
    const __half* srcBh = Wh + (size_t)(n0 + crow) * GK + cch * 8;
    const __half* srcBl = Wl + (size_t)(n0 + crow) * GK + cch * 8;

    auto issue = [&](int s) {
        const uint32_t stb = sbase + (uint32_t)(s % 3) * STG;
        CP_ASYNC16(stb + cdst,          srcA  + s * 16);
        CP_ASYNC16(stb + OFF_BH + cdst, srcBh + s * 16);
        if (twosplit) CP_ASYNC16(stb + OFF_BL + cdst, srcBl + s * 16);
        CP_COMMIT();
    };

    issue(0);
    issue(1);

    const int arow = wm * 64 + (lane & 15);
    const int ach  = lane >> 4;
    const int brow = wn * 32 + ((lane >> 4) & 1) * 8 + (lane & 7);
    const int bch  = (lane >> 3) & 1;

#pragma unroll
    for (int s = 0; s < NSTAGE; ++s) {
        if (s < NSTAGE - 1) { CP_WAIT(1); } else { CP_WAIT(0); }
        __syncthreads();
        if (s + 2 < NSTAGE) issue(s + 2);

        const uint32_t stb = sbase + (uint32_t)(s % 3) * STG;

        uint32_t ah[4][4], bh[4][2], bl[4][2];
#pragma unroll
        for (int i = 0; i < 4; ++i)
            LDSM_X4(ah[i], swz16(stb, arow + i * 16, ach));
#pragma unroll
        for (int jj = 0; jj < 2; ++jj) {
            uint32_t t[4];
            uint32_t ad = swz16(0, brow + jj * 16, bch);
            LDSM_X4(t, stb + OFF_BH + ad);
            bh[2 * jj][0] = t[0]; bh[2 * jj][1] = t[1];
            bh[2 * jj + 1][0] = t[2]; bh[2 * jj + 1][1] = t[3];
            if (twosplit) {
                LDSM_X4(t, stb + OFF_BL + ad);
                bl[2 * jj][0] = t[0]; bl[2 * jj][1] = t[1];
                bl[2 * jj + 1][0] = t[2]; bl[2 * jj + 1][1] = t[3];
            }
        }
        if (twosplit) {
#pragma unroll
            for (int i = 0; i < 4; ++i)
#pragma unroll
                for (int j = 0; j < 4; ++j) {
                    mma16816h(acc[i][j], ah[i], bh[j]);
                    mma16816h(acc[i][j], ah[i], bl[j]);
                }
        } else {
#pragma unroll
            for (int i = 0; i < 4; ++i)
#pragma unroll
                for (int j = 0; j < 4; ++j)
                    mma16816h(acc[i][j], ah[i], bh[j]);
        }
    }

    // --- epilogue: qk -> hi/lo split; v -> rounded single fp16
#pragma unroll
    for (int i = 0; i < 4; ++i) {
        int mb = m0 + wm * 64 + i * 16 + (lane >> 2);
#pragma unroll
        for (int j = 0; j < 4; ++j) {
            int nb = n0 + wn * 32 + j * 8 + (lane & 3) * 2;
            float bx = bias[nb], by = bias[nb + 1];
            float v00 = acc[i][j][0] + bx, v01 = acc[i][j][1] + by;
            float v10 = acc[i][j][2] + bx, v11 = acc[i][j][3] + by;
            if (twosplit) {
                uint32_t hp, lp;
                split2h(v00, v01, hp, lp);
                *(uint32_t*)&Ch[(size_t)mb * Nn + nb] = hp;
                *(uint32_t*)&Cl[(size_t)mb * Nn + nb] = lp;
                split2h(v10, v11, hp, lp);
                *(uint32_t*)&Ch[(size_t)(mb + 8) * Nn + nb] = hp;
                *(uint32_t*)&Cl[(size_t)(mb + 8) * Nn + nb] = lp;
            } else {
                __half2 h0 = __floats2half2_rn(v00, v01);
                __half2 h1 = __floats2half2_rn(v10, v11);
                *(uint32_t*)&Ch[(size_t)mb * Nn + nb]       = *(uint32_t*)&h0;
                *(uint32_t*)&Ch[(size_t)(mb + 8) * Nn + nb] = *(uint32_t*)&h1;
            }
        }
    }
}

// ---------------------------------------------------------------------------
// Proj GEMM: 1-split, fp32 out.
// ---------------------------------------------------------------------------
__global__ void __launch_bounds__(256, 2)
gemm_proj(const __half* __restrict__ Ah, const __half* __restrict__ Wh,
          const float* __restrict__ bias, float* __restrict__ Cf)
{
    extern __shared__ char smem[];
    const uint32_t sbase = smem_u32(smem);
    constexpr uint32_t STG = 8192u;
    constexpr uint32_t OFF_BH = 4096u;
    constexpr int NSTAGE = 16;
    constexpr int Nn = 256;

    const int tid  = threadIdx.x;
    const int lane = tid & 31;
    const int warp = tid >> 5;
    const int m0 = blockIdx.y * 128;
    const int n0 = blockIdx.x * 128;
    const int wm = warp & 1;
    const int wn = warp >> 1;

    float acc[4][4][4];
#pragma unroll
    for (int i = 0; i < 4; i++)
#pragma unroll
        for (int j = 0; j < 4; j++)
#pragma unroll
            for (int r = 0; r < 4; r++) acc[i][j][r] = 0.f;

    const int crow = tid >> 1;
    const int cch  = tid & 1;
    const uint32_t cdst = swz16(0, crow, cch);
    const __half* srcA  = Ah + (size_t)(m0 + crow) * GK + cch * 8;
    const __half* srcBh = Wh + (size_t)(n0 + crow) * GK + cch * 8;

    auto issue = [&](int s) {
        const uint32_t stb = sbase + (uint32_t)(s % 3) * STG;
        CP_ASYNC16(stb + cdst,          srcA  + s * 16);
        CP_ASYNC16(stb + OFF_BH + cdst, srcBh + s * 16);
        CP_COMMIT();
    };

    issue(0);
    issue(1);

    const int arow = wm * 64 + (lane & 15);
    const int ach  = lane >> 4;
    const int brow = wn * 32 + ((lane >> 4) & 1) * 8 + (lane & 7);
    const int bch  = (lane >> 3) & 1;

#pragma unroll
    for (int s = 0; s < NSTAGE; ++s) {
        if (s < NSTAGE - 1) { CP_WAIT(1); } else { CP_WAIT(0); }
        __syncthreads();
        if (s + 2 < NSTAGE) issue(s + 2);

        const uint32_t stb = sbase + (uint32_t)(s % 3) * STG;

        uint32_t ah[4][4], bh[4][2];
#pragma unroll
        for (int i = 0; i < 4; ++i)
            LDSM_X4(ah[i], swz16(stb, arow + i * 16, ach));
#pragma unroll
        for (int jj = 0; jj < 2; ++jj) {
            uint32_t t[4];
            uint32_t ad = swz16(0, brow + jj * 16, bch);
            LDSM_X4(t, stb + OFF_BH + ad);
            bh[2 * jj][0] = t[0]; bh[2 * jj][1] = t[1];
            bh[2 * jj + 1][0] = t[2]; bh[2 * jj + 1][1] = t[3];
        }
#pragma unroll
        for (int i = 0; i < 4; ++i)
#pragma unroll
            for (int j = 0; j < 4; ++j)
                mma16816h(acc[i][j], ah[i], bh[j]);
    }

#pragma unroll
    for (int i = 0; i < 4; ++i) {
        int mb = m0 + wm * 64 + i * 16 + (lane >> 2);
#pragma unroll
        for (int j = 0; j < 4; ++j) {
            int nb = n0 + wn * 32 + j * 8 + (lane & 3) * 2;
            float bx = bias[nb], by = bias[nb + 1];
            *(float2*)&Cf[(size_t)mb * Nn + nb] =
                make_float2(acc[i][j][0] + bx, acc[i][j][1] + by);
            *(float2*)&Cf[(size_t)(mb + 8) * Nn + nb] =
                make_float2(acc[i][j][2] + bx, acc[i][j][3] + by);
        }
    }
}

// ---------------------------------------------------------------------------
// Tensor-core attention: 5 smem arrays (Qh,Ql,Kh,Kl,Vh), 20KB/warp.
// S = QK^T 3-MMA split; O = P Vh 1-MMA (v pre-rounded upstream).
// Load loop: constant trip count, shift/mask only (no div/mod).
// ---------------------------------------------------------------------------
#define ATTN_SMEM (4 * 20480)

__global__ void __launch_bounds__(128)
attn_tc()
{
    extern __shared__ char asmem[];
    const uint32_t sbase = smem_u32(asmem);

    const int tid = threadIdx.x, warp = tid >> 5, lane = tid & 31;
    const int b = blockIdx.x >> 1;
    const int h = (blockIdx.x & 1) * 4 + warp;

    const uint32_t wb = sbase + warp * 20480u;
    const uint32_t Qh = wb, Ql = wb + 4096, Kh = wb + 8192, Kl = wb + 12288,
                   Vh = wb + 16384;

    // Zero V pad rows 50..63
    for (int i = lane; i < 112; i += 32) {
        int row = 50 + (i >> 3);
        STS64(Vh + row * 64 + (i & 7) * 8, 0u, 0u);
    }

    // cp.async fill: 5 arrays x 50 rows x 4 16B-chunks; shift/mask only.
    {
        const __half* baseH = g_qkvh + (size_t)b * NTOK * 768 + h * HD;
        const __half* baseL = g_qkvl + (size_t)b * NTOK * 768 + h * HD;
        const __half* srcs[5]  = { baseH, baseL, baseH + 256, baseL + 256, baseH + 512 };
        const uint32_t dsts[5] = { Qh, Ql, Kh, Kl, Vh };
#pragma unroll
        for (int arr = 0; arr < 5; ++arr) {
            const __half* s = srcs[arr];
            const uint32_t d = dsts[arr];
#pragma unroll
            for (int it = 0; it < 7; ++it) {
                int f = it * 32 + lane;
                if (f < 200) {
                    int row = f >> 2, c = f & 3;
                    CP_ASYNC16(swz(d, row, c), s + row * 768 + c * 8);
                }
            }
        }
        CP_COMMIT();
        CP_WAIT(0);
    }
    __syncwarp();

    const float* gbh = g_bias + h * (NTOK * NTOK);
    const int qrow = lane >> 2;
    const int j0l  = (lane & 3) * 2;

#pragma unroll
    for (int half = 0; half < 2; ++half) {
        float S[2][7][4];
#pragma unroll
        for (int m = 0; m < 2; m++)
#pragma unroll
            for (int nt = 0; nt < 7; nt++)
#pragma unroll
                for (int r = 0; r < 4; r++) S[m][nt][r] = 0.f;

        // ---- S = Q K^T (3-MMA split) ----
#pragma unroll
        for (int ks = 0; ks < 2; ++ks) {
            uint32_t qh[2][4], ql[2][4];
#pragma unroll
            for (int m = 0; m < 2; ++m) {
                int mt = half * 2 + m;
                int r = mt * 16 + (lane & 15);
                int ch = ks * 2 + (lane >> 4);
                LDSM_X4(qh[m], swz(Qh, r, ch));
                LDSM_X4(ql[m], swz(Ql, r, ch));
            }
#pragma unroll
            for (int nt = 0; nt < 7; ++nt) {
                uint32_t kh[2], kl[2];
                int r = nt * 8 + (lane & 7);
                int ch = ks * 2 + ((lane >> 3) & 1);
                LDSM_X2(kh, swz(Kh, r, ch));
                LDSM_X2(kl, swz(Kl, r, ch));
#pragma unroll
                for (int m = 0; m < 2; ++m) {
                    mma16816h(S[m][nt], qh[m], kh);
                    mma16816h(S[m][nt], qh[m], kl);
                    mma16816h(S[m][nt], ql[m], kh);
                }
            }
        }

        // ---- bias + mask ----
#pragma unroll
        for (int m = 0; m < 2; ++m) {
            int mt = half * 2 + m;
            int r0 = mt * 16 + qrow, r1 = r0 + 8;
#pragma unroll
            for (int nt = 0; nt < 7; ++nt) {
                int j0 = nt * 8 + j0l;
                if (j0 < NTOK) {
                    if (r0 < NTOK) {
                        float2 bv = *(const float2*)&gbh[r0 * NTOK + j0];
                        S[m][nt][0] += bv.x; S[m][nt][1] += bv.y;
                    }
                    if (r1 < NTOK) {
                        float2 bv = *(const float2*)&gbh[r1 * NTOK + j0];
                        S[m][nt][2] += bv.x; S[m][nt][3] += bv.y;
                    }
                } else {
                    S[m][nt][0] = -1e30f; S[m][nt][2] = -1e30f;
                }
                if (j0 + 1 >= NTOK) { S[m][nt][1] = -1e30f; S[m][nt][3] = -1e30f; }
            }
        }

        // ---- softmax (quad reductions) ----
#pragma unroll
        for (int m = 0; m < 2; ++m) {
            float mx0 = -1e30f, mx1 = -1e30f;
#pragma unroll
            for (int nt = 0; nt < 7; ++nt) {
                mx0 = fmaxf(mx0, fmaxf(S[m][nt][0], S[m][nt][1]));
                mx1 = fmaxf(mx1, fmaxf(S[m][nt][2], S[m][nt][3]));
            }
            mx0 = fmaxf(mx0, __shfl_xor_sync(0xffffffffu, mx0, 1));
            mx0 = fmaxf(mx0, __shfl_xor_sync(0xffffffffu, mx0, 2));
            mx1 = fmaxf(mx1, __shfl_xor_sync(0xffffffffu, mx1, 1));
            mx1 = fmaxf(mx1, __shfl_xor_sync(0xffffffffu, mx1, 2));
            float s0 = 0.f, s1 = 0.f;
#pragma unroll
            for (int nt = 0; nt < 7; ++nt) {
                S[m][nt][0] = __expf(S[m][nt][0] - mx0); s0 += S[m][nt][0];
                S[m][nt][1] = __expf(S[m][nt][1] - mx0); s0 += S[m][nt][1];
                S[m][nt][2] = __expf(S[m][nt][2] - mx1); s1 += S[m][nt][2];
                S[m][nt][3] = __expf(S[m][nt][3] - mx1); s1 += S[m][nt][3];
            }
            s0 += __shfl_xor_sync(0xffffffffu, s0, 1);
            s0 += __shfl_xor_sync(0xffffffffu, s0, 2);
            s1 += __shfl_xor_sync(0xffffffffu, s1, 1);
            s1 += __shfl_xor_sync(0xffffffffu, s1, 2);
            float i0 = 1.f / s0, i1 = 1.f / s1;
#pragma unroll
            for (int nt = 0; nt < 7; ++nt) {
                S[m][nt][0] *= i0; S[m][nt][1] *= i0;
                S[m][nt][2] *= i1; S[m][nt][3] *= i1;
            }
        }

        // ---- O = P Vh (1 MMA) ----
        float O[2][4][4];
#pragma unroll
        for (int m = 0; m < 2; m++)
#pragma unroll
            for (int nt = 0; nt < 4; nt++)
#pragma unroll
                for (int r = 0; r < 4; r++) O[m][nt][r] = 0.f;

#pragma unroll
        for (int kt = 0; kt < 4; ++kt) {
            uint32_t vh[2][4];
#pragma unroll
            for (int np = 0; np < 2; ++np) {
                int r = kt * 16 + (lane & 15);
                int ch = np * 2 + (lane >> 4);
                LDSM_X4_T(vh[np], swz(Vh, r, ch));
            }
#pragma unroll
            for (int m = 0; m < 2; ++m) {
                uint32_t ah[4];
                int ntA = 2 * kt, ntB = 2 * kt + 1;
                {
                    __half2 p0 = __floats2half2_rn(S[m][ntA][0], S[m][ntA][1]);
                    __half2 p1 = __floats2half2_rn(S[m][ntA][2], S[m][ntA][3]);
                    ah[0] = *(uint32_t*)&p0; ah[1] = *(uint32_t*)&p1;
                }
                if (ntB < 7) {
                    __half2 p0 = __floats2half2_rn(S[m][ntB][0], S[m][ntB][1]);
                    __half2 p1 = __floats2half2_rn(S[m][ntB][2], S[m][ntB][3]);
                    ah[2] = *(uint32_t*)&p0; ah[3] = *(uint32_t*)&p1;
                } else {
                    ah[2] = ah[3] = 0u;
                }
#pragma unroll
                for (int nt = 0; nt < 4; ++nt)
                    mma16816h(O[m][nt], ah, &vh[nt >> 1][(nt & 1) * 2]);
            }
        }

        // ---- store O rows < 50 as rounded fp16 ----
#pragma unroll
        for (int m = 0; m < 2; ++m) {
            int mt = half * 2 + m;
            int r0 = mt * 16 + qrow, r1 = r0 + 8;
#pragma unroll
            for (int nt = 0; nt < 4; ++nt) {
                int d0 = h * HD + nt * 8 + j0l;
                if (r0 < NTOK) {
                    __half2 hv = __floats2half2_rn(O[m][nt][0], O[m][nt][1]);
                    *(uint32_t*)&g_oh[(size_t)(b * NTOK + r0) * CDIM + d0] = *(uint32_t*)&hv;
                }
                if (r1 < NTOK) {
                    __half2 hv = __floats2half2_rn(O[m][nt][2], O[m][nt][3]);
                    *(uint32_t*)&g_oh[(size_t)(b * NTOK + r1) * CDIM + d0] = *(uint32_t*)&hv;
                }
            }
        }
    }
}

// ---------------------------------------------------------------------------
extern "C" void kernel_launch(void* const* d_in, const int* in_sizes, int n_in,
                              void* d_out, int out_size)
{
    const float* x          = (const float*)d_in[0];
    const float* qkv_w      = (const float*)d_in[1];
    const float* qkv_b      = (const float*)d_in[2];
    const float* proj_w     = (const float*)d_in[3];
    const float* proj_b     = (const float*)d_in[4];
    const float* bias_table = (const float*)d_in[5];
    const int*   rel_idx    = (const int*)d_in[6];
    float* out = (float*)d_out;

    const float scale = 0.17677669529663687f;   // 1/sqrt(32)

    static bool attr_set = false;
    if (!attr_set) {
        cudaFuncSetAttribute(gemm_qkv,  cudaFuncAttributeMaxDynamicSharedMemorySize, GEMM_SMEM2);
        cudaFuncSetAttribute(gemm_proj, cudaFuncAttributeMaxDynamicSharedMemorySize, GEMM_SMEM1);
        cudaFuncSetAttribute(attn_tc,   cudaFuncAttributeMaxDynamicSharedMemorySize, ATTN_SMEM);
        attr_set = true;
    }

    __half *xh, *wqh, *wql, *wph, *qh, *ql, *oh;
    float *qkvb;
    cudaGetSymbolAddress((void**)&xh,   g_xh);
    cudaGetSymbolAddress((void**)&wqh,  g_wqh);
    cudaGetSymbolAddress((void**)&wql,  g_wql);
    cudaGetSymbolAddress((void**)&wph,  g_wph);
    cudaGetSymbolAddress((void**)&qh,   g_qkvh);
    cudaGetSymbolAddress((void**)&ql,   g_qkvl);
    cudaGetSymbolAddress((void**)&oh,   g_oh);
    cudaGetSymbolAddress((void**)&qkvb, g_qkvb);

    // 1: fused prep
    prep_all<<<(SEG3 + 255) / 256, 256>>>(qkv_w, proj_w, bias_table, rel_idx, qkv_b, scale);
    // 2: x conversion
    conv_x<<<(MROWS * GK / 4 + 255) / 256, 256>>>(x, xh, MROWS * GK / 4);
    // 3: merged QKV
    gemm_qkv<<<dim3(6, MROWS / 128), 256, GEMM_SMEM2>>>(xh, wqh, wql, qkvb, qh, ql);
    // 4: attention  <- profiled launch
    attn_tc<<<BWIN * 2, 128, ATTN_SMEM>>>();
    // 5: proj
    gemm_proj<<<dim3(2, MROWS / 128), 256, GEMM_SMEM1>>>(oh, wph, proj_b, out);
}

// round 16
// speedup vs baseline: 1.2584x; 1.0395x over previous
#include <cuda_runtime.h>
#include <cuda_fp16.h>
#include <cstdint>
#include <cstddef>

// ---------------------------------------------------------------------------
// Problem constants
// ---------------------------------------------------------------------------
#define BWIN 2048
#define NTOK 50
#define CDIM 256
#define NH   8
#define HD   32
#define MROWS (BWIN * NTOK)      // 102400
#define GK   256                 // GEMM K

// ---------------------------------------------------------------------------
// Scratch (device globals; no allocation allowed)
// ---------------------------------------------------------------------------
__device__ __half g_xh[(size_t)MROWS * GK];        // x rounded fp16
__device__ __half g_qkvh[(size_t)MROWS * 768];     // qkv hi fp16 (v: rounded)
__device__ __half g_qkvl[(size_t)MROWS * 768];     // qkv lo fp16 (q,k only)
__device__ __half g_oh[(size_t)MROWS * CDIM];      // attention out fp16 (rounded)
__device__ __half g_wqh[768 * GK], g_wql[768 * GK];
__device__ __half g_wph[CDIM * GK];
__device__ float  g_qkvb[768];                     // qkv bias (q-scaled)
__device__ float  g_bias[NH * NTOK * NTOK + 64];   // expanded relpos bias

// ---------------------------------------------------------------------------
// Helpers
// ---------------------------------------------------------------------------
__device__ __forceinline__ uint32_t smem_u32(const void* p) {
    uint32_t a;
    asm("{ .reg .u64 t; cvta.to.shared.u64 t, %1; cvt.u32.u64 %0, t; }" : "=r"(a) : "l"(p));
    return a;
}

__device__ __forceinline__ void split2h(float x, float y, uint32_t& hp, uint32_t& lp) {
    __half2 h = __floats2half2_rn(x, y);
    hp = *reinterpret_cast<uint32_t*>(&h);
    float rx = x - __low2float(h);
    float ry = y - __high2float(h);
    __half2 l = __floats2half2_rn(rx, ry);
    lp = *reinterpret_cast<uint32_t*>(&l);
}

#define LDSM_X4(r, a) asm volatile( \
    "ldmatrix.sync.aligned.m8n8.x4.shared.b16 {%0,%1,%2,%3}, [%4];" \
    : "=r"((r)[0]), "=r"((r)[1]), "=r"((r)[2]), "=r"((r)[3]) : "r"(a))
#define LDSM_X2(r, a) asm volatile( \
    "ldmatrix.sync.aligned.m8n8.x2.shared.b16 {%0,%1}, [%2];" \
    : "=r"((r)[0]), "=r"((r)[1]) : "r"(a))
#define LDSM_X4_T(r, a) asm volatile( \
    "ldmatrix.sync.aligned.m8n8.x4.trans.shared.b16 {%0,%1,%2,%3}, [%4];" \
    : "=r"((r)[0]), "=r"((r)[1]), "=r"((r)[2]), "=r"((r)[3]) : "r"(a))

__device__ __forceinline__ void mma16816h(float* d, const uint32_t* a, const uint32_t* b) {
    asm volatile(
        "mma.sync.aligned.m16n8k16.row.col.f32.f16.f16.f32 "
        "{%0,%1,%2,%3},{%4,%5,%6,%7},{%8,%9},{%0,%1,%2,%3};"
        : "+f"(d[0]), "+f"(d[1]), "+f"(d[2]), "+f"(d[3])
        : "r"(a[0]), "r"(a[1]), "r"(a[2]), "r"(a[3]), "r"(b[0]), "r"(b[1]));
}

#define CP_ASYNC16(dst, src) asm volatile( \
    "cp.async.cg.shared.global [%0], [%1], 16;" :: "r"(dst), "l"(src))
#define CP_COMMIT() asm volatile("cp.async.commit_group;" ::: "memory")
#define CP_WAIT(n)  asm volatile("cp.async.wait_group %0;" :: "n"(n) : "memory")
#define STS64(a, x, y) asm volatile("st.shared.v2.b32 [%0], {%1,%2};" :: "r"(a), "r"(x), "r"(y) : "memory")

// 64B-row swizzle (attention tiles)
__device__ __forceinline__ uint32_t swz(uint32_t base, int r, int ch) {
    return base + r * 64 + 16 * (ch ^ ((r >> 1) & 3));
}
// 32B-row swizzle (GEMM k16 stages)
__device__ __forceinline__ uint32_t swz16(uint32_t base, int r, int ch) {
    return base + r * 32 + 16 * (ch ^ ((r >> 2) & 1));
}

// ---------------------------------------------------------------------------
// x converter
// ---------------------------------------------------------------------------
__global__ void conv_x(const float* __restrict__ src, __half* __restrict__ dh, int n4)
{
    int i = blockIdx.x * 256 + threadIdx.x;
    if (i >= n4) return;
    float4 v = ((const float4*)src)[i];
    __half2 h01 = __floats2half2_rn(v.x, v.y);
    __half2 h23 = __floats2half2_rn(v.z, v.w);
    ((uint2*)dh)[i] = make_uint2(*(uint32_t*)&h01, *(uint32_t*)&h23);
}

// ---------------------------------------------------------------------------
// Fused prep
// ---------------------------------------------------------------------------
#define SEG0 49152
#define SEG1 (SEG0 + 16384)
#define SEG2 (SEG1 + 20000)
#define SEG3 (SEG2 + 768)

__global__ void prep_all(const float* __restrict__ qkv_w,
                         const float* __restrict__ proj_w,
                         const float* __restrict__ bt,
                         const int*   __restrict__ ri,
                         const float* __restrict__ qkv_b,
                         float scale)
{
    int idx = blockIdx.x * 256 + threadIdx.x;
    if (idx < SEG0) {
        float4 v = ((const float4*)qkv_w)[idx];
        if (idx < 16384) { v.x *= scale; v.y *= scale; v.z *= scale; v.w *= scale; }
        uint32_t h01, l01, h23, l23;
        split2h(v.x, v.y, h01, l01);
        split2h(v.z, v.w, h23, l23);
        ((uint2*)g_wqh)[idx] = make_uint2(h01, h23);
        ((uint2*)g_wql)[idx] = make_uint2(l01, l23);
    } else if (idx < SEG1) {
        int i = idx - SEG0;
        float4 v = ((const float4*)proj_w)[i];
        __half2 h01 = __floats2half2_rn(v.x, v.y);
        __half2 h23 = __floats2half2_rn(v.z, v.w);
        ((uint2*)g_wph)[i] = make_uint2(*(uint32_t*)&h01, *(uint32_t*)&h23);
    } else if (idx < SEG2) {
        int i = idx - SEG1;
        int h = i / (NTOK * NTOK);
        int rem = i - h * NTOK * NTOK;
        int r = rem / NTOK, c = rem - r * NTOK;
        float v = 0.f;
        if (r > 0 && c > 0) v = bt[ri[(r - 1) * 49 + (c - 1)] * NH + h];
        g_bias[i] = v;
    } else if (idx < SEG3) {
        int i = idx - SEG2;
        g_qkvb[i] = qkv_b[i] * (i < 256 ? scale : 1.f);
    }
}

// ---------------------------------------------------------------------------
// Merged QKV GEMM: cols 0..511 (qk) 2-split hi/lo out; cols 512..767 (v)
// 1-split, ROUNDED single fp16 out (no lo write).
// ---------------------------------------------------------------------------
#define GEMM_SMEM2 (3 * 12288)
#define GEMM_SMEM1 (3 * 8192)

__global__ void __launch_bounds__(256, 2)
gemm_qkv(const __half* __restrict__ Ah,
         const __half* __restrict__ Wh, const __half* __restrict__ Wl,
         const float* __restrict__ bias,
         __half* __restrict__ Ch, __half* __restrict__ Cl)
{
    extern __shared__ char smem[];
    const uint32_t sbase = smem_u32(smem);
    constexpr uint32_t STG = 12288u;
    constexpr uint32_t OFF_BH = 4096u, OFF_BL = 8192u;
    constexpr int NSTAGE = 16;
    constexpr int Nn = 768;

    const bool twosplit = (blockIdx.x < 4);
    const int tid  = threadIdx.x;
    const int lane = tid & 31;
    const int warp = tid >> 5;
    const int m0 = blockIdx.y * 128;
    const int n0 = blockIdx.x * 128;
    const int wm = warp & 1;
    const int wn = warp >> 1;

    float acc[4][4][4];
#pragma unroll
    for (int i = 0; i < 4; i++)
#pragma unroll
        for (int j = 0; j < 4; j++)
#pragma unroll
            for (int r = 0; r < 4; r++) acc[i][j][r] = 0.f;

    const int crow = tid >> 1;
    const int cch  = tid & 1;
    const uint32_t cdst = swz16(0, crow, cch);
    const __half* srcA  = Ah + (size_t)(m0 + crow) * GK + cch * 8;
    const __half* srcBh = Wh + (size_t)(n0 + crow) * GK + cch * 8;
    const __half* srcBl = Wl + (size_t)(n0 + crow) * GK + cch * 8;

    auto issue = [&](int s) {
        const uint32_t stb = sbase + (uint32_t)(s % 3) * STG;
        CP_ASYNC16(stb + cdst,          srcA  + s * 16);
        CP_ASYNC16(stb + OFF_BH + cdst, srcBh + s * 16);
        if (twosplit) CP_ASYNC16(stb + OFF_BL + cdst, srcBl + s * 16);
        CP_COMMIT();
    };

    issue(0);
    issue(1);

    const int arow = wm * 64 + (lane & 15);
    const int ach  = lane >> 4;
    const int brow = wn * 32 + ((lane >> 4) & 1) * 8 + (lane & 7);
    const int bch  = (lane >> 3) & 1;

#pragma unroll
    for (int s = 0; s < NSTAGE; ++s) {
        if (s < NSTAGE - 1) { CP_WAIT(1); } else { CP_WAIT(0); }
        __syncthreads();
        if (s + 2 < NSTAGE) issue(s + 2);

        const uint32_t stb = sbase + (uint32_t)(s % 3) * STG;

        uint32_t ah[4][4], bh[4][2], bl[4][2];
#pragma unroll
        for (int i = 0; i < 4; ++i)
            LDSM_X4(ah[i], swz16(stb, arow + i * 16, ach));
#pragma unroll
        for (int jj = 0; jj < 2; ++jj) {
            uint32_t t[4];
            uint32_t ad = swz16(0, brow + jj * 16, bch);
            LDSM_X4(t, stb + OFF_BH + ad);
            bh[2 * jj][0] = t[0]; bh[2 * jj][1] = t[1];
            bh[2 * jj + 1][0] = t[2]; bh[2 * jj + 1][1] = t[3];
            if (twosplit) {
                LDSM_X4(t, stb + OFF_BL + ad);
                bl[2 * jj][0] = t[0]; bl[2 * jj][1] = t[1];
                bl[2 * jj + 1][0] = t[2]; bl[2 * jj + 1][1] = t[3];
            }
        }
        if (twosplit) {
#pragma unroll
            for (int i = 0; i < 4; ++i)
#pragma unroll
                for (int j = 0; j < 4; ++j) {
                    mma16816h(acc[i][j], ah[i], bh[j]);
                    mma16816h(acc[i][j], ah[i], bl[j]);
                }
        } else {
#pragma unroll
            for (int i = 0; i < 4; ++i)
#pragma unroll
                for (int j = 0; j < 4; ++j)
                    mma16816h(acc[i][j], ah[i], bh[j]);
        }
    }

    // --- epilogue: qk -> hi/lo split; v -> rounded single fp16
#pragma unroll
    for (int i = 0; i < 4; ++i) {
        int mb = m0 + wm * 64 + i * 16 + (lane >> 2);
#pragma unroll
        for (int j = 0; j < 4; ++j) {
            int nb = n0 + wn * 32 + j * 8 + (lane & 3) * 2;
            float bx = bias[nb], by = bias[nb + 1];
            float v00 = acc[i][j][0] + bx, v01 = acc[i][j][1] + by;
            float v10 = acc[i][j][2] + bx, v11 = acc[i][j][3] + by;
            if (twosplit) {
                uint32_t hp, lp;
                split2h(v00, v01, hp, lp);
                *(uint32_t*)&Ch[(size_t)mb * Nn + nb] = hp;
                *(uint32_t*)&Cl[(size_t)mb * Nn + nb] = lp;
                split2h(v10, v11, hp, lp);
                *(uint32_t*)&Ch[(size_t)(mb + 8) * Nn + nb] = hp;
                *(uint32_t*)&Cl[(size_t)(mb + 8) * Nn + nb] = lp;
            } else {
                __half2 h0 = __floats2half2_rn(v00, v01);
                __half2 h1 = __floats2half2_rn(v10, v11);
                *(uint32_t*)&Ch[(size_t)mb * Nn + nb]       = *(uint32_t*)&h0;
                *(uint32_t*)&Ch[(size_t)(mb + 8) * Nn + nb] = *(uint32_t*)&h1;
            }
        }
    }
}

// ---------------------------------------------------------------------------
// Proj GEMM: 1-split, fp32 out.
// ---------------------------------------------------------------------------
__global__ void __launch_bounds__(256, 2)
gemm_proj(const __half* __restrict__ Ah, const __half* __restrict__ Wh,
          const float* __restrict__ bias, float* __restrict__ Cf)
{
    extern __shared__ char smem[];
    const uint32_t sbase = smem_u32(smem);
    constexpr uint32_t STG = 8192u;
    constexpr uint32_t OFF_BH = 4096u;
    constexpr int NSTAGE = 16;
    constexpr int Nn = 256;

    const int tid  = threadIdx.x;
    const int lane = tid & 31;
    const int warp = tid >> 5;
    const int m0 = blockIdx.y * 128;
    const int n0 = blockIdx.x * 128;
    const int wm = warp & 1;
    const int wn = warp >> 1;

    float acc[4][4][4];
#pragma unroll
    for (int i = 0; i < 4; i++)
#pragma unroll
        for (int j = 0; j < 4; j++)
#pragma unroll
            for (int r = 0; r < 4; r++) acc[i][j][r] = 0.f;

    const int crow = tid >> 1;
    const int cch  = tid & 1;
    const uint32_t cdst = swz16(0, crow, cch);
    const __half* srcA  = Ah + (size_t)(m0 + crow) * GK + cch * 8;
    const __half* srcBh = Wh + (size_t)(n0 + crow) * GK + cch * 8;

    auto issue = [&](int s) {
        const uint32_t stb = sbase + (uint32_t)(s % 3) * STG;
        CP_ASYNC16(stb + cdst,          srcA  + s * 16);
        CP_ASYNC16(stb + OFF_BH + cdst, srcBh + s * 16);
        CP_COMMIT();
    };

    issue(0);
    issue(1);

    const int arow = wm * 64 + (lane & 15);
    const int ach  = lane >> 4;
    const int brow = wn * 32 + ((lane >> 4) & 1) * 8 + (lane & 7);
    const int bch  = (lane >> 3) & 1;

#pragma unroll
    for (int s = 0; s < NSTAGE; ++s) {
        if (s < NSTAGE - 1) { CP_WAIT(1); } else { CP_WAIT(0); }
        __syncthreads();
        if (s + 2 < NSTAGE) issue(s + 2);

        const uint32_t stb = sbase + (uint32_t)(s % 3) * STG;

        uint32_t ah[4][4], bh[4][2];
#pragma unroll
        for (int i = 0; i < 4; ++i)
            LDSM_X4(ah[i], swz16(stb, arow + i * 16, ach));
#pragma unroll
        for (int jj = 0; jj < 2; ++jj) {
            uint32_t t[4];
            uint32_t ad = swz16(0, brow + jj * 16, bch);
            LDSM_X4(t, stb + OFF_BH + ad);
            bh[2 * jj][0] = t[0]; bh[2 * jj][1] = t[1];
            bh[2 * jj + 1][0] = t[2]; bh[2 * jj + 1][1] = t[3];
        }
#pragma unroll
        for (int i = 0; i < 4; ++i)
#pragma unroll
            for (int j = 0; j < 4; ++j)
                mma16816h(acc[i][j], ah[i], bh[j]);
    }

#pragma unroll
    for (int i = 0; i < 4; ++i) {
        int mb = m0 + wm * 64 + i * 16 + (lane >> 2);
#pragma unroll
        for (int j = 0; j < 4; ++j) {
            int nb = n0 + wn * 32 + j * 8 + (lane & 3) * 2;
            float bx = bias[nb], by = bias[nb + 1];
            *(float2*)&Cf[(size_t)mb * Nn + nb] =
                make_float2(acc[i][j][0] + bx, acc[i][j][1] + by);
            *(float2*)&Cf[(size_t)(mb + 8) * Nn + nb] =
                make_float2(acc[i][j][2] + bx, acc[i][j][3] + by);
        }
    }
}

// ---------------------------------------------------------------------------
// Tensor-core attention: 5 smem arrays per warp, packed to 18432 B
// (Qh/Ql/Kh/Kl at 56-row 3584 B, Vh 64-row 4096 B) -> 3 CTAs/SM.
// LDSM reads of padded rows 56-63 spill into the next array; garbage lands
// only in output rows >= 50, which are masked/not stored.
// ---------------------------------------------------------------------------
#define WSTRIDE 18432u
#define ATTN_SMEM (4 * 18432)

__global__ void __launch_bounds__(128, 3)
attn_tc()
{
    extern __shared__ char asmem[];
    const uint32_t sbase = smem_u32(asmem);

    const int tid = threadIdx.x, warp = tid >> 5, lane = tid & 31;
    const int b = blockIdx.x >> 1;
    const int h = (blockIdx.x & 1) * 4 + warp;

    const uint32_t wb = sbase + warp * WSTRIDE;
    const uint32_t Qh = wb, Ql = wb + 3584, Kh = wb + 7168, Kl = wb + 10752,
                   Vh = wb + 14336;

    // Zero V pad rows 50..63
    for (int i = lane; i < 112; i += 32) {
        int row = 50 + (i >> 3);
        STS64(Vh + row * 64 + (i & 7) * 8, 0u, 0u);
    }

    // cp.async fill: 5 arrays x 50 rows x 4 16B-chunks; shift/mask only.
    {
        const __half* baseH = g_qkvh + (size_t)b * NTOK * 768 + h * HD;
        const __half* baseL = g_qkvl + (size_t)b * NTOK * 768 + h * HD;
        const __half* srcs[5]  = { baseH, baseL, baseH + 256, baseL + 256, baseH + 512 };
        const uint32_t dsts[5] = { Qh, Ql, Kh, Kl, Vh };
#pragma unroll
        for (int arr = 0; arr < 5; ++arr) {
            const __half* s = srcs[arr];
            const uint32_t d = dsts[arr];
#pragma unroll
            for (int it = 0; it < 7; ++it) {
                int f = it * 32 + lane;
                if (f < 200) {
                    int row = f >> 2, c = f & 3;
                    CP_ASYNC16(swz(d, row, c), s + row * 768 + c * 8);
                }
            }
        }
        CP_COMMIT();
        CP_WAIT(0);
    }
    __syncwarp();

    const float* gbh = g_bias + h * (NTOK * NTOK);
    const int qrow = lane >> 2;
    const int j0l  = (lane & 3) * 2;

#pragma unroll
    for (int half = 0; half < 2; ++half) {
        float S[2][7][4];
#pragma unroll
        for (int m = 0; m < 2; m++)
#pragma unroll
            for (int nt = 0; nt < 7; nt++)
#pragma unroll
                for (int r = 0; r < 4; r++) S[m][nt][r] = 0.f;

        // ---- S = Q K^T (3-MMA split) ----
#pragma unroll
        for (int ks = 0; ks < 2; ++ks) {
            uint32_t qh[2][4], ql[2][4];
#pragma unroll
            for (int m = 0; m < 2; ++m) {
                int mt = half * 2 + m;
                int r = mt * 16 + (lane & 15);
                int ch = ks * 2 + (lane >> 4);
                LDSM_X4(qh[m], swz(Qh, r, ch));
                LDSM_X4(ql[m], swz(Ql, r, ch));
            }
#pragma unroll
            for (int nt = 0; nt < 7; ++nt) {
                uint32_t kh[2], kl[2];
                int r = nt * 8 + (lane & 7);
                int ch = ks * 2 + ((lane >> 3) & 1);
                LDSM_X2(kh, swz(Kh, r, ch));
                LDSM_X2(kl, swz(Kl, r, ch));
#pragma unroll
                for (int m = 0; m < 2; ++m) {
                    mma16816h(S[m][nt], qh[m], kh);
                    mma16816h(S[m][nt], qh[m], kl);
                    mma16816h(S[m][nt], ql[m], kh);
                }
            }
        }

        // ---- bias + mask ----
#pragma unroll
        for (int m = 0; m < 2; ++m) {
            int mt = half * 2 + m;
            int r0 = mt * 16 + qrow, r1 = r0 + 8;
#pragma unroll
            for (int nt = 0; nt < 7; ++nt) {
                int j0 = nt * 8 + j0l;
                if (j0 < NTOK) {
                    if (r0 < NTOK) {
                        float2 bv = *(const float2*)&gbh[r0 * NTOK + j0];
                        S[m][nt][0] += bv.x; S[m][nt][1] += bv.y;
                    }
                    if (r1 < NTOK) {
                        float2 bv = *(const float2*)&gbh[r1 * NTOK + j0];
                        S[m][nt][2] += bv.x; S[m][nt][3] += bv.y;
                    }
                } else {
                    S[m][nt][0] = -1e30f; S[m][nt][2] = -1e30f;
                }
                if (j0 + 1 >= NTOK) { S[m][nt][1] = -1e30f; S[m][nt][3] = -1e30f; }
            }
        }

        // ---- softmax (quad reductions) ----
#pragma unroll
        for (int m = 0; m < 2; ++m) {
            float mx0 = -1e30f, mx1 = -1e30f;
#pragma unroll
            for (int nt = 0; nt < 7; ++nt) {
                mx0 = fmaxf(mx0, fmaxf(S[m][nt][0], S[m][nt][1]));
                mx1 = fmaxf(mx1, fmaxf(S[m][nt][2], S[m][nt][3]));
            }
            mx0 = fmaxf(mx0, __shfl_xor_sync(0xffffffffu, mx0, 1));
            mx0 = fmaxf(mx0, __shfl_xor_sync(0xffffffffu, mx0, 2));
            mx1 = fmaxf(mx1, __shfl_xor_sync(0xffffffffu, mx1, 1));
            mx1 = fmaxf(mx1, __shfl_xor_sync(0xffffffffu, mx1, 2));
            float s0 = 0.f, s1 = 0.f;
#pragma unroll
            for (int nt = 0; nt < 7; ++nt) {
                S[m][nt][0] = __expf(S[m][nt][0] - mx0); s0 += S[m][nt][0];
                S[m][nt][1] = __expf(S[m][nt][1] - mx0); s0 += S[m][nt][1];
                S[m][nt][2] = __expf(S[m][nt][2] - mx1); s1 += S[m][nt][2];
                S[m][nt][3] = __expf(S[m][nt][3] - mx1); s1 += S[m][nt][3];
            }
            s0 += __shfl_xor_sync(0xffffffffu, s0, 1);
            s0 += __shfl_xor_sync(0xffffffffu, s0, 2);
            s1 += __shfl_xor_sync(0xffffffffu, s1, 1);
            s1 += __shfl_xor_sync(0xffffffffu, s1, 2);
            float i0 = 1.f / s0, i1 = 1.f / s1;
#pragma unroll
            for (int nt = 0; nt < 7; ++nt) {
                S[m][nt][0] *= i0; S[m][nt][1] *= i0;
                S[m][nt][2] *= i1; S[m][nt][3] *= i1;
            }
        }

        // ---- O = P Vh (1 MMA) ----
        float O[2][4][4];
#pragma unroll
        for (int m = 0; m < 2; m++)
#pragma unroll
            for (int nt = 0; nt < 4; nt++)
#pragma unroll
                for (int r = 0; r < 4; r++) O[m][nt][r] = 0.f;

#pragma unroll
        for (int kt = 0; kt < 4; ++kt) {
            uint32_t vh[2][4];
#pragma unroll
            for (int np = 0; np < 2; ++np) {
                int r = kt * 16 + (lane & 15);
                int ch = np * 2 + (lane >> 4);
                LDSM_X4_T(vh[np], swz(Vh, r, ch));
            }
#pragma unroll
            for (int m = 0; m < 2; ++m) {
                uint32_t ah[4];
                int ntA = 2 * kt, ntB = 2 * kt + 1;
                {
                    __half2 p0 = __floats2half2_rn(S[m][ntA][0], S[m][ntA][1]);
                    __half2 p1 = __floats2half2_rn(S[m][ntA][2], S[m][ntA][3]);
                    ah[0] = *(uint32_t*)&p0; ah[1] = *(uint32_t*)&p1;
                }
                if (ntB < 7) {
                    __half2 p0 = __floats2half2_rn(S[m][ntB][0], S[m][ntB][1]);
                    __half2 p1 = __floats2half2_rn(S[m][ntB][2], S[m][ntB][3]);
                    ah[2] = *(uint32_t*)&p0; ah[3] = *(uint32_t*)&p1;
                } else {
                    ah[2] = ah[3] = 0u;
                }
#pragma unroll
                for (int nt = 0; nt < 4; ++nt)
                    mma16816h(O[m][nt], ah, &vh[nt >> 1][(nt & 1) * 2]);
            }
        }

        // ---- store O rows < 50 as rounded fp16 ----
#pragma unroll
        for (int m = 0; m < 2; ++m) {
            int mt = half * 2 + m;
            int r0 = mt * 16 + qrow, r1 = r0 + 8;
#pragma unroll
            for (int nt = 0; nt < 4; ++nt) {
                int d0 = h * HD + nt * 8 + j0l;
                if (r0 < NTOK) {
                    __half2 hv = __floats2half2_rn(O[m][nt][0], O[m][nt][1]);
                    *(uint32_t*)&g_oh[(size_t)(b * NTOK + r0) * CDIM + d0] = *(uint32_t*)&hv;
                }
                if (r1 < NTOK) {
                    __half2 hv = __floats2half2_rn(O[m][nt][2], O[m][nt][3]);
                    *(uint32_t*)&g_oh[(size_t)(b * NTOK + r1) * CDIM + d0] = *(uint32_t*)&hv;
                }
            }
        }
    }
}

// ---------------------------------------------------------------------------
extern "C" void kernel_launch(void* const* d_in, const int* in_sizes, int n_in,
                              void* d_out, int out_size)
{
    const float* x          = (const float*)d_in[0];
    const float* qkv_w      = (const float*)d_in[1];
    const float* qkv_b      = (const float*)d_in[2];
    const float* proj_w     = (const float*)d_in[3];
    const float* proj_b     = (const float*)d_in[4];
    const float* bias_table = (const float*)d_in[5];
    const int*   rel_idx    = (const int*)d_in[6];
    float* out = (float*)d_out;

    const float scale = 0.17677669529663687f;   // 1/sqrt(32)

    static bool attr_set = false;
    if (!attr_set) {
        cudaFuncSetAttribute(gemm_qkv,  cudaFuncAttributeMaxDynamicSharedMemorySize, GEMM_SMEM2);
        cudaFuncSetAttribute(gemm_proj, cudaFuncAttributeMaxDynamicSharedMemorySize, GEMM_SMEM1);
        cudaFuncSetAttribute(attn_tc,   cudaFuncAttributeMaxDynamicSharedMemorySize, ATTN_SMEM);
        attr_set = true;
    }

    __half *xh, *wqh, *wql, *wph, *qh, *ql, *oh;
    float *qkvb;
    cudaGetSymbolAddress((void**)&xh,   g_xh);
    cudaGetSymbolAddress((void**)&wqh,  g_wqh);
    cudaGetSymbolAddress((void**)&wql,  g_wql);
    cudaGetSymbolAddress((void**)&wph,  g_wph);
    cudaGetSymbolAddress((void**)&qh,   g_qkvh);
    cudaGetSymbolAddress((void**)&ql,   g_qkvl);
    cudaGetSymbolAddress((void**)&oh,   g_oh);
    cudaGetSymbolAddress((void**)&qkvb, g_qkvb);

    // 1: fused prep
    prep_all<<<(SEG3 + 255) / 256, 256>>>(qkv_w, proj_w, bias_table, rel_idx, qkv_b, scale);
    // 2: x conversion
    conv_x<<<(MROWS * GK / 4 + 255) / 256, 256>>>(x, xh, MROWS * GK / 4);
    // 3: merged QKV
    gemm_qkv<<<dim3(6, MROWS / 128), 256, GEMM_SMEM2>>>(xh, wqh, wql, qkvb, qh, ql);
    // 4: attention  <- profiled launch
    attn_tc<<<BWIN * 2, 128, ATTN_SMEM>>>();
    // 5: proj
    gemm_proj<<<dim3(2, MROWS / 128), 256, GEMM_SMEM1>>>(oh, wph, proj_b, out);
}

// round 17
// speedup vs baseline: 1.4222x; 1.1302x over previous
#include <cuda_runtime.h>
#include <cuda_fp16.h>
#include <cstdint>
#include <cstddef>

// ---------------------------------------------------------------------------
// Problem constants
// ---------------------------------------------------------------------------
#define BWIN 2048
#define NTOK 50
#define CDIM 256
#define NH   8
#define HD   32
#define MROWS (BWIN * NTOK)      // 102400
#define GK   256                 // GEMM K

// ---------------------------------------------------------------------------
// Scratch (device globals; no allocation allowed)
// ---------------------------------------------------------------------------
__device__ __half g_xh[(size_t)MROWS * GK];        // x rounded fp16
__device__ __half g_qkvh[(size_t)MROWS * 768];     // qkv hi fp16 (v: rounded)
__device__ __half g_qkvl[(size_t)MROWS * 768];     // qkv lo fp16 (q,k only)
__device__ __half g_oh[(size_t)MROWS * CDIM];      // attention out fp16 (rounded)
__device__ __half g_wqh[768 * GK];                 // qkv W rounded fp16 (q rows scaled)
__device__ __half g_wph[CDIM * GK];                // proj W rounded fp16
__device__ float  g_qkvb[768];                     // qkv bias (q-scaled)
__device__ float  g_bias[NH * NTOK * NTOK + 64];   // expanded relpos bias

// ---------------------------------------------------------------------------
// Helpers
// ---------------------------------------------------------------------------
__device__ __forceinline__ uint32_t smem_u32(const void* p) {
    uint32_t a;
    asm("{ .reg .u64 t; cvta.to.shared.u64 t, %1; cvt.u32.u64 %0, t; }" : "=r"(a) : "l"(p));
    return a;
}

__device__ __forceinline__ void split2h(float x, float y, uint32_t& hp, uint32_t& lp) {
    __half2 h = __floats2half2_rn(x, y);
    hp = *reinterpret_cast<uint32_t*>(&h);
    float rx = x - __low2float(h);
    float ry = y - __high2float(h);
    __half2 l = __floats2half2_rn(rx, ry);
    lp = *reinterpret_cast<uint32_t*>(&l);
}

#define LDSM_X4(r, a) asm volatile( \
    "ldmatrix.sync.aligned.m8n8.x4.shared.b16 {%0,%1,%2,%3}, [%4];" \
    : "=r"((r)[0]), "=r"((r)[1]), "=r"((r)[2]), "=r"((r)[3]) : "r"(a))
#define LDSM_X2(r, a) asm volatile( \
    "ldmatrix.sync.aligned.m8n8.x2.shared.b16 {%0,%1}, [%2];" \
    : "=r"((r)[0]), "=r"((r)[1]) : "r"(a))
#define LDSM_X4_T(r, a) asm volatile( \
    "ldmatrix.sync.aligned.m8n8.x4.trans.shared.b16 {%0,%1,%2,%3}, [%4];" \
    : "=r"((r)[0]), "=r"((r)[1]), "=r"((r)[2]), "=r"((r)[3]) : "r"(a))

__device__ __forceinline__ void mma16816h(float* d, const uint32_t* a, const uint32_t* b) {
    asm volatile(
        "mma.sync.aligned.m16n8k16.row.col.f32.f16.f16.f32 "
        "{%0,%1,%2,%3},{%4,%5,%6,%7},{%8,%9},{%0,%1,%2,%3};"
        : "+f"(d[0]), "+f"(d[1]), "+f"(d[2]), "+f"(d[3])
        : "r"(a[0]), "r"(a[1]), "r"(a[2]), "r"(a[3]), "r"(b[0]), "r"(b[1]));
}

#define CP_ASYNC16(dst, src) asm volatile( \
    "cp.async.cg.shared.global [%0], [%1], 16;" :: "r"(dst), "l"(src))
#define CP_COMMIT() asm volatile("cp.async.commit_group;" ::: "memory")
#define CP_WAIT(n)  asm volatile("cp.async.wait_group %0;" :: "n"(n) : "memory")
#define STS64(a, x, y) asm volatile("st.shared.v2.b32 [%0], {%1,%2};" :: "r"(a), "r"(x), "r"(y) : "memory")

// 64B-row swizzle (attention tiles)
__device__ __forceinline__ uint32_t swz(uint32_t base, int r, int ch) {
    return base + r * 64 + 16 * (ch ^ ((r >> 1) & 3));
}
// 32B-row swizzle (GEMM k16 stages)
__device__ __forceinline__ uint32_t swz16(uint32_t base, int r, int ch) {
    return base + r * 32 + 16 * (ch ^ ((r >> 2) & 1));
}

// ---------------------------------------------------------------------------
// x converter
// ---------------------------------------------------------------------------
__global__ void conv_x(const float* __restrict__ src, __half* __restrict__ dh, int n4)
{
    int i = blockIdx.x * 256 + threadIdx.x;
    if (i >= n4) return;
    float4 v = ((const float4*)src)[i];
    __half2 h01 = __floats2half2_rn(v.x, v.y);
    __half2 h23 = __floats2half2_rn(v.z, v.w);
    ((uint2*)dh)[i] = make_uint2(*(uint32_t*)&h01, *(uint32_t*)&h23);
}

// ---------------------------------------------------------------------------
// Fused prep: qkv W round (+q scale), proj W round, bias expand, qkv bias
// ---------------------------------------------------------------------------
#define SEG0 49152
#define SEG1 (SEG0 + 16384)
#define SEG2 (SEG1 + 20000)
#define SEG3 (SEG2 + 768)

__global__ void prep_all(const float* __restrict__ qkv_w,
                         const float* __restrict__ proj_w,
                         const float* __restrict__ bt,
                         const int*   __restrict__ ri,
                         const float* __restrict__ qkv_b,
                         float scale)
{
    int idx = blockIdx.x * 256 + threadIdx.x;
    if (idx < SEG0) {
        float4 v = ((const float4*)qkv_w)[idx];
        if (idx < 16384) { v.x *= scale; v.y *= scale; v.z *= scale; v.w *= scale; }
        __half2 h01 = __floats2half2_rn(v.x, v.y);
        __half2 h23 = __floats2half2_rn(v.z, v.w);
        ((uint2*)g_wqh)[idx] = make_uint2(*(uint32_t*)&h01, *(uint32_t*)&h23);
    } else if (idx < SEG1) {
        int i = idx - SEG0;
        float4 v = ((const float4*)proj_w)[i];
        __half2 h01 = __floats2half2_rn(v.x, v.y);
        __half2 h23 = __floats2half2_rn(v.z, v.w);
        ((uint2*)g_wph)[i] = make_uint2(*(uint32_t*)&h01, *(uint32_t*)&h23);
    } else if (idx < SEG2) {
        int i = idx - SEG1;
        int h = i / (NTOK * NTOK);
        int rem = i - h * NTOK * NTOK;
        int r = rem / NTOK, c = rem - r * NTOK;
        float v = 0.f;
        if (r > 0 && c > 0) v = bt[ri[(r - 1) * 49 + (c - 1)] * NH + h];
        g_bias[i] = v;
    } else if (idx < SEG3) {
        int i = idx - SEG2;
        g_qkvb[i] = qkv_b[i] * (i < 256 ? scale : 1.f);
    }
}

// ---------------------------------------------------------------------------
// Merged QKV GEMM, uniform 1-split (W rounded): 1 MMA per tile.
// Epilogue: cols 0..511 (qk) emit fp16 hi/lo split (attention needs the
// residual for its 3-MMA S); cols 512..767 (v) emit rounded fp16 only.
// ---------------------------------------------------------------------------
#define GEMM_SMEM (3 * 8192)

__global__ void __launch_bounds__(256, 2)
gemm_qkv(const __half* __restrict__ Ah, const __half* __restrict__ Wh,
         const float* __restrict__ bias,
         __half* __restrict__ Ch, __half* __restrict__ Cl)
{
    extern __shared__ char smem[];
    const uint32_t sbase = smem_u32(smem);
    constexpr uint32_t STG = 8192u;
    constexpr uint32_t OFF_BH = 4096u;
    constexpr int NSTAGE = 16;
    constexpr int Nn = 768;

    const bool qkpart = (blockIdx.x < 4);
    const int tid  = threadIdx.x;
    const int lane = tid & 31;
    const int warp = tid >> 5;
    const int m0 = blockIdx.y * 128;
    const int n0 = blockIdx.x * 128;
    const int wm = warp & 1;
    const int wn = warp >> 1;

    float acc[4][4][4];
#pragma unroll
    for (int i = 0; i < 4; i++)
#pragma unroll
        for (int j = 0; j < 4; j++)
#pragma unroll
            for (int r = 0; r < 4; r++) acc[i][j][r] = 0.f;

    const int crow = tid >> 1;
    const int cch  = tid & 1;
    const uint32_t cdst = swz16(0, crow, cch);
    const __half* srcA  = Ah + (size_t)(m0 + crow) * GK + cch * 8;
    const __half* srcBh = Wh + (size_t)(n0 + crow) * GK + cch * 8;

    auto issue = [&](int s) {
        const uint32_t stb = sbase + (uint32_t)(s % 3) * STG;
        CP_ASYNC16(stb + cdst,          srcA  + s * 16);
        CP_ASYNC16(stb + OFF_BH + cdst, srcBh + s * 16);
        CP_COMMIT();
    };

    issue(0);
    issue(1);

    const int arow = wm * 64 + (lane & 15);
    const int ach  = lane >> 4;
    const int brow = wn * 32 + ((lane >> 4) & 1) * 8 + (lane & 7);
    const int bch  = (lane >> 3) & 1;

#pragma unroll
    for (int s = 0; s < NSTAGE; ++s) {
        if (s < NSTAGE - 1) { CP_WAIT(1); } else { CP_WAIT(0); }
        __syncthreads();
        if (s + 2 < NSTAGE) issue(s + 2);

        const uint32_t stb = sbase + (uint32_t)(s % 3) * STG;

        uint32_t ah[4][4], bh[4][2];
#pragma unroll
        for (int i = 0; i < 4; ++i)
            LDSM_X4(ah[i], swz16(stb, arow + i * 16, ach));
#pragma unroll
        for (int jj = 0; jj < 2; ++jj) {
            uint32_t t[4];
            uint32_t ad = swz16(0, brow + jj * 16, bch);
            LDSM_X4(t, stb + OFF_BH + ad);
            bh[2 * jj][0] = t[0]; bh[2 * jj][1] = t[1];
            bh[2 * jj + 1][0] = t[2]; bh[2 * jj + 1][1] = t[3];
        }
#pragma unroll
        for (int i = 0; i < 4; ++i)
#pragma unroll
            for (int j = 0; j < 4; ++j)
                mma16816h(acc[i][j], ah[i], bh[j]);
    }

    // --- epilogue: qk -> hi/lo split; v -> rounded single fp16
#pragma unroll
    for (int i = 0; i < 4; ++i) {
        int mb = m0 + wm * 64 + i * 16 + (lane >> 2);
#pragma unroll
        for (int j = 0; j < 4; ++j) {
            int nb = n0 + wn * 32 + j * 8 + (lane & 3) * 2;
            float bx = bias[nb], by = bias[nb + 1];
            float v00 = acc[i][j][0] + bx, v01 = acc[i][j][1] + by;
            float v10 = acc[i][j][2] + bx, v11 = acc[i][j][3] + by;
            if (qkpart) {
                uint32_t hp, lp;
                split2h(v00, v01, hp, lp);
                *(uint32_t*)&Ch[(size_t)mb * Nn + nb] = hp;
                *(uint32_t*)&Cl[(size_t)mb * Nn + nb] = lp;
                split2h(v10, v11, hp, lp);
                *(uint32_t*)&Ch[(size_t)(mb + 8) * Nn + nb] = hp;
                *(uint32_t*)&Cl[(size_t)(mb + 8) * Nn + nb] = lp;
            } else {
                __half2 h0 = __floats2half2_rn(v00, v01);
                __half2 h1 = __floats2half2_rn(v10, v11);
                *(uint32_t*)&Ch[(size_t)mb * Nn + nb]       = *(uint32_t*)&h0;
                *(uint32_t*)&Ch[(size_t)(mb + 8) * Nn + nb] = *(uint32_t*)&h1;
            }
        }
    }
}

// ---------------------------------------------------------------------------
// Proj GEMM: 1-split, fp32 out.
// ---------------------------------------------------------------------------
__global__ void __launch_bounds__(256, 2)
gemm_proj(const __half* __restrict__ Ah, const __half* __restrict__ Wh,
          const float* __restrict__ bias, float* __restrict__ Cf)
{
    extern __shared__ char smem[];
    const uint32_t sbase = smem_u32(smem);
    constexpr uint32_t STG = 8192u;
    constexpr uint32_t OFF_BH = 4096u;
    constexpr int NSTAGE = 16;
    constexpr int Nn = 256;

    const int tid  = threadIdx.x;
    const int lane = tid & 31;
    const int warp = tid >> 5;
    const int m0 = blockIdx.y * 128;
    const int n0 = blockIdx.x * 128;
    const int wm = warp & 1;
    const int wn = warp >> 1;

    float acc[4][4][4];
#pragma unroll
    for (int i = 0; i < 4; i++)
#pragma unroll
        for (int j = 0; j < 4; j++)
#pragma unroll
            for (int r = 0; r < 4; r++) acc[i][j][r] = 0.f;

    const int crow = tid >> 1;
    const int cch  = tid & 1;
    const uint32_t cdst = swz16(0, crow, cch);
    const __half* srcA  = Ah + (size_t)(m0 + crow) * GK + cch * 8;
    const __half* srcBh = Wh + (size_t)(n0 + crow) * GK + cch * 8;

    auto issue = [&](int s) {
        const uint32_t stb = sbase + (uint32_t)(s % 3) * STG;
        CP_ASYNC16(stb + cdst,          srcA  + s * 16);
        CP_ASYNC16(stb + OFF_BH + cdst, srcBh + s * 16);
        CP_COMMIT();
    };

    issue(0);
    issue(1);

    const int arow = wm * 64 + (lane & 15);
    const int ach  = lane >> 4;
    const int brow = wn * 32 + ((lane >> 4) & 1) * 8 + (lane & 7);
    const int bch  = (lane >> 3) & 1;

#pragma unroll
    for (int s = 0; s < NSTAGE; ++s) {
        if (s < NSTAGE - 1) { CP_WAIT(1); } else { CP_WAIT(0); }
        __syncthreads();
        if (s + 2 < NSTAGE) issue(s + 2);

        const uint32_t stb = sbase + (uint32_t)(s % 3) * STG;

        uint32_t ah[4][4], bh[4][2];
#pragma unroll
        for (int i = 0; i < 4; ++i)
            LDSM_X4(ah[i], swz16(stb, arow + i * 16, ach));
#pragma unroll
        for (int jj = 0; jj < 2; ++jj) {
            uint32_t t[4];
            uint32_t ad = swz16(0, brow + jj * 16, bch);
            LDSM_X4(t, stb + OFF_BH + ad);
            bh[2 * jj][0] = t[0]; bh[2 * jj][1] = t[1];
            bh[2 * jj + 1][0] = t[2]; bh[2 * jj + 1][1] = t[3];
        }
#pragma unroll
        for (int i = 0; i < 4; ++i)
#pragma unroll
            for (int j = 0; j < 4; ++j)
                mma16816h(acc[i][j], ah[i], bh[j]);
    }

#pragma unroll
    for (int i = 0; i < 4; ++i) {
        int mb = m0 + wm * 64 + i * 16 + (lane >> 2);
#pragma unroll
        for (int j = 0; j < 4; ++j) {
            int nb = n0 + wn * 32 + j * 8 + (lane & 3) * 2;
            float bx = bias[nb], by = bias[nb + 1];
            *(float2*)&Cf[(size_t)mb * Nn + nb] =
                make_float2(acc[i][j][0] + bx, acc[i][j][1] + by);
            *(float2*)&Cf[(size_t)(mb + 8) * Nn + nb] =
                make_float2(acc[i][j][2] + bx, acc[i][j][3] + by);
        }
    }
}

// ---------------------------------------------------------------------------
// Tensor-core attention (unchanged from R15 winner): 5 arrays packed to
// 18432 B/warp -> 3 CTAs/SM. S = QK^T 3-MMA split; O = P Vh 1-MMA.
// ---------------------------------------------------------------------------
#define WSTRIDE 18432u
#define ATTN_SMEM (4 * 18432)

__global__ void __launch_bounds__(128, 3)
attn_tc()
{
    extern __shared__ char asmem[];
    const uint32_t sbase = smem_u32(asmem);

    const int tid = threadIdx.x, warp = tid >> 5, lane = tid & 31;
    const int b = blockIdx.x >> 1;
    const int h = (blockIdx.x & 1) * 4 + warp;

    const uint32_t wb = sbase + warp * WSTRIDE;
    const uint32_t Qh = wb, Ql = wb + 3584, Kh = wb + 7168, Kl = wb + 10752,
                   Vh = wb + 14336;

    // Zero V pad rows 50..63
    for (int i = lane; i < 112; i += 32) {
        int row = 50 + (i >> 3);
        STS64(Vh + row * 64 + (i & 7) * 8, 0u, 0u);
    }

    // cp.async fill: 5 arrays x 50 rows x 4 16B-chunks; shift/mask only.
    {
        const __half* baseH = g_qkvh + (size_t)b * NTOK * 768 + h * HD;
        const __half* baseL = g_qkvl + (size_t)b * NTOK * 768 + h * HD;
        const __half* srcs[5]  = { baseH, baseL, baseH + 256, baseL + 256, baseH + 512 };
        const uint32_t dsts[5] = { Qh, Ql, Kh, Kl, Vh };
#pragma unroll
        for (int arr = 0; arr < 5; ++arr) {
            const __half* s = srcs[arr];
            const uint32_t d = dsts[arr];
#pragma unroll
            for (int it = 0; it < 7; ++it) {
                int f = it * 32 + lane;
                if (f < 200) {
                    int row = f >> 2, c = f & 3;
                    CP_ASYNC16(swz(d, row, c), s + row * 768 + c * 8);
                }
            }
        }
        CP_COMMIT();
        CP_WAIT(0);
    }
    __syncwarp();

    const float* gbh = g_bias + h * (NTOK * NTOK);
    const int qrow = lane >> 2;
    const int j0l  = (lane & 3) * 2;

#pragma unroll
    for (int half = 0; half < 2; ++half) {
        float S[2][7][4];
#pragma unroll
        for (int m = 0; m < 2; m++)
#pragma unroll
            for (int nt = 0; nt < 7; nt++)
#pragma unroll
                for (int r = 0; r < 4; r++) S[m][nt][r] = 0.f;

        // ---- S = Q K^T (3-MMA split) ----
#pragma unroll
        for (int ks = 0; ks < 2; ++ks) {
            uint32_t qh[2][4], ql[2][4];
#pragma unroll
            for (int m = 0; m < 2; ++m) {
                int mt = half * 2 + m;
                int r = mt * 16 + (lane & 15);
                int ch = ks * 2 + (lane >> 4);
                LDSM_X4(qh[m], swz(Qh, r, ch));
                LDSM_X4(ql[m], swz(Ql, r, ch));
            }
#pragma unroll
            for (int nt = 0; nt < 7; ++nt) {
                uint32_t kh[2], kl[2];
                int r = nt * 8 + (lane & 7);
                int ch = ks * 2 + ((lane >> 3) & 1);
                LDSM_X2(kh, swz(Kh, r, ch));
                LDSM_X2(kl, swz(Kl, r, ch));
#pragma unroll
                for (int m = 0; m < 2; ++m) {
                    mma16816h(S[m][nt], qh[m], kh);
                    mma16816h(S[m][nt], qh[m], kl);
                    mma16816h(S[m][nt], ql[m], kh);
                }
            }
        }

        // ---- bias + mask ----
#pragma unroll
        for (int m = 0; m < 2; ++m) {
            int mt = half * 2 + m;
            int r0 = mt * 16 + qrow, r1 = r0 + 8;
#pragma unroll
            for (int nt = 0; nt < 7; ++nt) {
                int j0 = nt * 8 + j0l;
                if (j0 < NTOK) {
                    if (r0 < NTOK) {
                        float2 bv = *(const float2*)&gbh[r0 * NTOK + j0];
                        S[m][nt][0] += bv.x; S[m][nt][1] += bv.y;
                    }
                    if (r1 < NTOK) {
                        float2 bv = *(const float2*)&gbh[r1 * NTOK + j0];
                        S[m][nt][2] += bv.x; S[m][nt][3] += bv.y;
                    }
                } else {
                    S[m][nt][0] = -1e30f; S[m][nt][2] = -1e30f;
                }
                if (j0 + 1 >= NTOK) { S[m][nt][1] = -1e30f; S[m][nt][3] = -1e30f; }
            }
        }

        // ---- softmax (quad reductions) ----
#pragma unroll
        for (int m = 0; m < 2; ++m) {
            float mx0 = -1e30f, mx1 = -1e30f;
#pragma unroll
            for (int nt = 0; nt < 7; ++nt) {
                mx0 = fmaxf(mx0, fmaxf(S[m][nt][0], S[m][nt][1]));
                mx1 = fmaxf(mx1, fmaxf(S[m][nt][2], S[m][nt][3]));
            }
            mx0 = fmaxf(mx0, __shfl_xor_sync(0xffffffffu, mx0, 1));
            mx0 = fmaxf(mx0, __shfl_xor_sync(0xffffffffu, mx0, 2));
            mx1 = fmaxf(mx1, __shfl_xor_sync(0xffffffffu, mx1, 1));
            mx1 = fmaxf(mx1, __shfl_xor_sync(0xffffffffu, mx1, 2));
            float s0 = 0.f, s1 = 0.f;
#pragma unroll
            for (int nt = 0; nt < 7; ++nt) {
                S[m][nt][0] = __expf(S[m][nt][0] - mx0); s0 += S[m][nt][0];
                S[m][nt][1] = __expf(S[m][nt][1] - mx0); s0 += S[m][nt][1];
                S[m][nt][2] = __expf(S[m][nt][2] - mx1); s1 += S[m][nt][2];
                S[m][nt][3] = __expf(S[m][nt][3] - mx1); s1 += S[m][nt][3];
            }
            s0 += __shfl_xor_sync(0xffffffffu, s0, 1);
            s0 += __shfl_xor_sync(0xffffffffu, s0, 2);
            s1 += __shfl_xor_sync(0xffffffffu, s1, 1);
            s1 += __shfl_xor_sync(0xffffffffu, s1, 2);
            float i0 = 1.f / s0, i1 = 1.f / s1;
#pragma unroll
            for (int nt = 0; nt < 7; ++nt) {
                S[m][nt][0] *= i0; S[m][nt][1] *= i0;
                S[m][nt][2] *= i1; S[m][nt][3] *= i1;
            }
        }

        // ---- O = P Vh (1 MMA) ----
        float O[2][4][4];
#pragma unroll
        for (int m = 0; m < 2; m++)
#pragma unroll
            for (int nt = 0; nt < 4; nt++)
#pragma unroll
                for (int r = 0; r < 4; r++) O[m][nt][r] = 0.f;

#pragma unroll
        for (int kt = 0; kt < 4; ++kt) {
            uint32_t vh[2][4];
#pragma unroll
            for (int np = 0; np < 2; ++np) {
                int r = kt * 16 + (lane & 15);
                int ch = np * 2 + (lane >> 4);
                LDSM_X4_T(vh[np], swz(Vh, r, ch));
            }
#pragma unroll
            for (int m = 0; m < 2; ++m) {
                uint32_t ah[4];
                int ntA = 2 * kt, ntB = 2 * kt + 1;
                {
                    __half2 p0 = __floats2half2_rn(S[m][ntA][0], S[m][ntA][1]);
                    __half2 p1 = __floats2half2_rn(S[m][ntA][2], S[m][ntA][3]);
                    ah[0] = *(uint32_t*)&p0; ah[1] = *(uint32_t*)&p1;
                }
                if (ntB < 7) {
                    __half2 p0 = __floats2half2_rn(S[m][ntB][0], S[m][ntB][1]);
                    __half2 p1 = __floats2half2_rn(S[m][ntB][2], S[m][ntB][3]);
                    ah[2] = *(uint32_t*)&p0; ah[3] = *(uint32_t*)&p1;
                } else {
                    ah[2] = ah[3] = 0u;
                }
#pragma unroll
                for (int nt = 0; nt < 4; ++nt)
                    mma16816h(O[m][nt], ah, &vh[nt >> 1][(nt & 1) * 2]);
            }
        }

        // ---- store O rows < 50 as rounded fp16 ----
#pragma unroll
        for (int m = 0; m < 2; ++m) {
            int mt = half * 2 + m;
            int r0 = mt * 16 + qrow, r1 = r0 + 8;
#pragma unroll
            for (int nt = 0; nt < 4; ++nt) {
                int d0 = h * HD + nt * 8 + j0l;
                if (r0 < NTOK) {
                    __half2 hv = __floats2half2_rn(O[m][nt][0], O[m][nt][1]);
                    *(uint32_t*)&g_oh[(size_t)(b * NTOK + r0) * CDIM + d0] = *(uint32_t*)&hv;
                }
                if (r1 < NTOK) {
                    __half2 hv = __floats2half2_rn(O[m][nt][2], O[m][nt][3]);
                    *(uint32_t*)&g_oh[(size_t)(b * NTOK + r1) * CDIM + d0] = *(uint32_t*)&hv;
                }
            }
        }
    }
}

// ---------------------------------------------------------------------------
extern "C" void kernel_launch(void* const* d_in, const int* in_sizes, int n_in,
                              void* d_out, int out_size)
{
    const float* x          = (const float*)d_in[0];
    const float* qkv_w      = (const float*)d_in[1];
    const float* qkv_b      = (const float*)d_in[2];
    const float* proj_w     = (const float*)d_in[3];
    const float* proj_b     = (const float*)d_in[4];
    const float* bias_table = (const float*)d_in[5];
    const int*   rel_idx    = (const int*)d_in[6];
    float* out = (float*)d_out;

    const float scale = 0.17677669529663687f;   // 1/sqrt(32)

    static bool attr_set = false;
    if (!attr_set) {
        cudaFuncSetAttribute(gemm_qkv,  cudaFuncAttributeMaxDynamicSharedMemorySize, GEMM_SMEM);
        cudaFuncSetAttribute(gemm_proj, cudaFuncAttributeMaxDynamicSharedMemorySize, GEMM_SMEM);
        cudaFuncSetAttribute(attn_tc,   cudaFuncAttributeMaxDynamicSharedMemorySize, ATTN_SMEM);
        attr_set = true;
    }

    __half *xh, *wqh, *wph, *qh, *ql, *oh;
    float *qkvb;
    cudaGetSymbolAddress((void**)&xh,   g_xh);
    cudaGetSymbolAddress((void**)&wqh,  g_wqh);
    cudaGetSymbolAddress((void**)&wph,  g_wph);
    cudaGetSymbolAddress((void**)&qh,   g_qkvh);
    cudaGetSymbolAddress((void**)&ql,   g_qkvl);
    cudaGetSymbolAddress((void**)&oh,   g_oh);
    cudaGetSymbolAddress((void**)&qkvb, g_qkvb);

    // 1: fused prep
    prep_all<<<(SEG3 + 255) / 256, 256>>>(qkv_w, proj_w, bias_table, rel_idx, qkv_b, scale);
    // 2: x conversion
    conv_x<<<(MROWS * GK / 4 + 255) / 256, 256>>>(x, xh, MROWS * GK / 4);
    // 3: merged QKV, uniform 1-split
    gemm_qkv<<<dim3(6, MROWS / 128), 256, GEMM_SMEM>>>(xh, wqh, qkvb, qh, ql);
    // 4: attention  <- profiled launch
    attn_tc<<<BWIN * 2, 128, ATTN_SMEM>>>();
    // 5: proj
    gemm_proj<<<dim3(2, MROWS / 128), 256, GEMM_SMEM>>>(oh, wph, proj_b, out);
}